// round 5
// baseline (speedup 1.0000x reference)
#include <cuda_runtime.h>
#include <cstdint>
#include <math.h>

#define NB 128   // batch
#define NS 100   // seq len
#define NM 50    // memory slots
#define ND 128   // dim
#define T  320   // threads: 256 compute + 64 mem

#define NROW (NB * NS)     // 12800 (b,s) rows
#define RPB  32            // rows per precompute block
#define KS   132           // padded key row stride

// Scratch for precomputed attention weights and qe@W1b+b1
__device__ float g_attn[NB * NS * NM];
__device__ float g_q1[NB * NS * ND];

// packed fp32x2 helpers (sm_100+)
#define PACK2(d, xx, yy) asm("mov.b64 %0, {%1, %2};" : "=l"(d) : "r"(__float_as_uint(xx)), "r"(__float_as_uint(yy)))
#define DUP2(d, xx)      asm("mov.b64 %0, {%1, %1};" : "=l"(d) : "r"(__float_as_uint(xx)))
#define FMA2(d, a, b, c) asm("fma.rn.f32x2 %0, %1, %2, %3;" : "=l"(d) : "l"(a), "l"(b), "l"(c))
#define BAR256()         asm volatile("bar.sync 1, 256;" ::: "memory")

// ---------------------------------------------------------------------------
// K1: tiled batched precompute (unchanged from R3, ~3.7us)
// ---------------------------------------------------------------------------
#define P_KEY  0
#define P_W1B  (NM * KS)
#define P_QE   (P_W1B + ND * ND)
#define P_B1   (P_QE + RPB * ND)
#define P_IDS  (P_B1 + ND)
#define P_TOTF (P_IDS + RPB)
#define PRE_SMEM_BYTES (P_TOTF * 4)

__global__ __launch_bounds__(256, 1)
void precompute_kernel(const int* __restrict__ qseq,
                       const float* __restrict__ emb,
                       const float* __restrict__ keym,
                       const float* __restrict__ vu_w1,
                       const float* __restrict__ vu_b1) {
    extern __shared__ float ps[];
    float* sKey = ps + P_KEY;
    float* sW1b = ps + P_W1B;
    float* sQe  = ps + P_QE;
    float* sB1  = ps + P_B1;
    int*   sIds = (int*)(ps + P_IDS);

    const int t  = threadIdx.x;
    const int r0 = blockIdx.x * RPB;

    if (t < RPB) sIds[t] = qseq[r0 + t];

    for (int i = t; i < NM * ND / 4; i += 256) {
        const int m = i / 32, c4 = i % 32;
        *(float4*)(sKey + m * KS + c4 * 4) = ((const float4*)keym)[i];
    }
    {
        const float4* src = (const float4*)(vu_w1 + ND * ND);
        for (int i = t; i < ND * ND / 4; i += 256) ((float4*)sW1b)[i] = src[i];
    }
    if (t < ND) sB1[t] = vu_b1[t];
    __syncthreads();

    for (int i = t; i < RPB * 32; i += 256) {
        const int row = i >> 5, c4 = i & 31;
        const float4* src = (const float4*)(emb + (size_t)sIds[row] * ND);
        *(float4*)(sQe + row * ND + c4 * 4) = src[c4];
    }
    __syncthreads();

    {
        const int wid = t >> 5, lid = t & 31;
        const int mB = (lid < NM - 32) ? lid + 32 : lid;
        float acc0[4] = {0, 0, 0, 0}, acc1[4] = {0, 0, 0, 0};
        const float* kA = sKey + lid * KS;
        const float* kB = sKey + mB * KS;
#pragma unroll
        for (int k4 = 0; k4 < 32; k4++) {
            const float4 a = *(const float4*)(kA + k4 * 4);
            const float4 b = *(const float4*)(kB + k4 * 4);
#pragma unroll
            for (int r = 0; r < 4; r++) {
                const float4 q = *(const float4*)(sQe + (wid * 4 + r) * ND + k4 * 4);
                acc0[r] = fmaf(q.x, a.x, fmaf(q.y, a.y, fmaf(q.z, a.z, fmaf(q.w, a.w, acc0[r]))));
                acc1[r] = fmaf(q.x, b.x, fmaf(q.y, b.y, fmaf(q.z, b.z, fmaf(q.w, b.w, acc1[r]))));
            }
        }
        const bool hasB = (lid < NM - 32);
#pragma unroll
        for (int r = 0; r < 4; r++) {
            float v0 = acc0[r];
            float v1 = hasB ? acc1[r] : -1e30f;
            float mx = fmaxf(v0, v1);
#pragma unroll
            for (int o = 16; o; o >>= 1) mx = fmaxf(mx, __shfl_xor_sync(0xffffffffu, mx, o));
            float e0 = __expf(v0 - mx);
            float e1 = hasB ? __expf(v1 - mx) : 0.f;
            float sum = e0 + e1;
#pragma unroll
            for (int o = 16; o; o >>= 1) sum += __shfl_xor_sync(0xffffffffu, sum, o);
            const float inv = 1.f / sum;
            float* dst = g_attn + (size_t)(r0 + wid * 4 + r) * NM;
            dst[lid] = e0 * inv;
            if (hasB) dst[lid + 32] = e1 * inv;
        }
    }

    {
        const int cg = t & 31;
        const int rg = t >> 5;
        float4 acc[4] = {{0,0,0,0},{0,0,0,0},{0,0,0,0},{0,0,0,0}};
#pragma unroll 8
        for (int k4 = 0; k4 < 32; k4++) {
            const float4 w0 = *(const float4*)(sW1b + (k4 * 4 + 0) * ND + cg * 4);
            const float4 w1 = *(const float4*)(sW1b + (k4 * 4 + 1) * ND + cg * 4);
            const float4 w2 = *(const float4*)(sW1b + (k4 * 4 + 2) * ND + cg * 4);
            const float4 w3 = *(const float4*)(sW1b + (k4 * 4 + 3) * ND + cg * 4);
#pragma unroll
            for (int r = 0; r < 4; r++) {
                const float4 q = *(const float4*)(sQe + (rg * 4 + r) * ND + k4 * 4);
                acc[r].x = fmaf(q.x, w0.x, fmaf(q.y, w1.x, fmaf(q.z, w2.x, fmaf(q.w, w3.x, acc[r].x))));
                acc[r].y = fmaf(q.x, w0.y, fmaf(q.y, w1.y, fmaf(q.z, w2.y, fmaf(q.w, w3.y, acc[r].y))));
                acc[r].z = fmaf(q.x, w0.z, fmaf(q.y, w1.z, fmaf(q.z, w2.z, fmaf(q.w, w3.z, acc[r].z))));
                acc[r].w = fmaf(q.x, w0.w, fmaf(q.y, w1.w, fmaf(q.z, w2.w, fmaf(q.w, w3.w, acc[r].w))));
            }
        }
        const float4 b4 = *(const float4*)(sB1 + cg * 4);
#pragma unroll
        for (int r = 0; r < 4; r++) {
            float4 o = acc[r];
            o.x += b4.x; o.y += b4.y; o.z += b4.z; o.w += b4.w;
            *(float4*)(g_q1 + (size_t)(r0 + rg * 4 + r) * ND + cg * 4) = o;
        }
    }
}

// ---------------------------------------------------------------------------
// K2: warp-specialized recurrent kernel.
//  threads 0..255  : compute warps — read-combine, A, B, C chain
//  threads 256..319: mem warps — v state in registers; apply update for step
//                    s-1 and produce r0/g/c for step s+1, overlapped.
// Identity: read_{s} = r0 - e_{s-1}.g + c*a_{s-1},
//   r0 = w_s . v_{s-1},  g = sum_m w_s[m] w_{s-1}[m] v_{s-1}[m][:],
//   c  = sum_m w_s[m] w_{s-1}[m]   (with v already updated through step s-2).
// ---------------------------------------------------------------------------
// smem layout (floats)
#define SM_W1   0
#define SM_W2   16384
#define SM_ATTN 32768          // 100*50 = 5000
#define SM_P    37768          // 1024 scratch
#define SM_READ 38792          // 128
#define SM_H    38920          // 128
#define SM_UP   39048          // 128
#define SM_E    39176          // 2 x 128 (parity)
#define SM_A    39432          // 2 x 128
#define SM_R0   39688          // 2 x 128
#define SM_G    39944          // 2 x 128
#define SM_C    40200          // 2
#define SM_TOTF 40204
#define SMEM_BYTES (SM_TOTF * 4)

__global__ __launch_bounds__(T, 1)
void recurrent_kernel(const int* __restrict__ qseq,
                      const float* __restrict__ emb,
                      const float* __restrict__ vu_w1,
                      const float* __restrict__ vu_w2,
                      const float* __restrict__ vu_b2,
                      const float* __restrict__ er_w,
                      const float* __restrict__ er_b,
                      const float* __restrict__ ad_w,
                      const float* __restrict__ ad_b,
                      const float* __restrict__ out_w1,
                      const float* __restrict__ out_b1,
                      const float* __restrict__ out_w2,
                      const float* __restrict__ out_b2,
                      float* __restrict__ out) {
    extern __shared__ float sm[];
    float* sW1   = sm + SM_W1;
    float* sW2   = sm + SM_W2;
    float* sAttn = sm + SM_ATTN;
    float* sP    = sm + SM_P;
    float* sRead = sm + SM_READ;
    float* sH    = sm + SM_H;
    float* sUp   = sm + SM_UP;

    const int b = blockIdx.x;
    const int t = threadIdx.x;

    // ---- shared init ----
    for (int i = t; i < ND * ND; i += T) { sW1[i] = vu_w1[i]; sW2[i] = vu_w2[i]; }
    for (int i = t; i < NS * NM; i += T) sAttn[i] = g_attn[b * NS * NM + i];
    for (int i = t; i < 2 * ND * 4 + 4; i += T) sm[SM_E + i] = 0.f;  // e/a/r0/g/c buffers

    // ---- per-role register state ----
    // compute: er/ad weights packed f32x2: thread owns 4 outputs (jq) x 32 k (ks)
    const int jq = t & 63;
    const int ks = (t >> 6) & 3;
    unsigned long long ea2[64];
    float biasO = 0.f, b2r = 0.f;
    if (t < 256) {
        const float* src = (jq < 32) ? (er_w + jq * 4) : (ad_w + (jq - 32) * 4);
#pragma unroll
        for (int kk = 0; kk < 32; kk++) {
            const float4 w4 = *(const float4*)(src + (ks * 32 + kk) * ND);
            PACK2(ea2[kk * 2],     w4.x, w4.y);
            PACK2(ea2[kk * 2 + 1], w4.z, w4.w);
        }
        if (t < ND) { biasO = er_b[t]; b2r = vu_b2[t]; }
        else        { biasO = ad_b[t - ND]; }
    }
    // mem: v state (float2 per d-pair, all 50 slots) in registers
    const int u = t - 256;         // 0..63 for mem threads
    float2 v2[NM];
    if (t >= 256) {
#pragma unroll
        for (int m = 0; m < NM; m++) { v2[m].x = 0.f; v2[m].y = 0.f; }
    }

    // compute stage mappings
    const int j4 = (t & 31) * 4;
    const int kg = (t >> 5) & 7;

    __syncthreads();

    const float* q1b = g_q1 + b * NS * ND;

    for (int s = 0; s < NS; s++) {
        const int par  = s & 1;         // r0/g/c for this step; e/a written this step
        const int parm = (s + 1) & 1;   // e/a from previous step; r0/g/c written for next

        if (t < 256) {
            // prefetch q1 (consumed in A-reduce)
            float q1v = 0.f;
            if (t < ND) q1v = q1b[s * ND + t];

            // ---- R: read_s = r0 - e.g + c*a ----
            if (t < ND) {
                const float e  = sm[SM_E  + parm * ND + t];
                const float a  = sm[SM_A  + parm * ND + t];
                const float r0 = sm[SM_R0 + par  * ND + t];
                const float gg = sm[SM_G  + par  * ND + t];
                const float cc = sm[SM_C  + par];
                sRead[t] = fmaf(cc, a, fmaf(-e, gg, r0));
            }
            BAR256();

            // ---- A: h = tanh(read @ W1a + q1) ----
            {
                float4 acc = {0.f, 0.f, 0.f, 0.f};
                const float4* xr = (const float4*)(sRead + kg * 16);
#pragma unroll
                for (int k4 = 0; k4 < 4; k4++) {
                    const float4 x = xr[k4];
                    const float* wb = sW1 + (kg * 16 + k4 * 4) * ND + j4;
                    const float4 w0 = *(const float4*)(wb);
                    const float4 w1 = *(const float4*)(wb + ND);
                    const float4 w2 = *(const float4*)(wb + 2 * ND);
                    const float4 w3 = *(const float4*)(wb + 3 * ND);
                    acc.x = fmaf(x.x, w0.x, fmaf(x.y, w1.x, fmaf(x.z, w2.x, fmaf(x.w, w3.x, acc.x))));
                    acc.y = fmaf(x.x, w0.y, fmaf(x.y, w1.y, fmaf(x.z, w2.y, fmaf(x.w, w3.y, acc.y))));
                    acc.z = fmaf(x.x, w0.z, fmaf(x.y, w1.z, fmaf(x.z, w2.z, fmaf(x.w, w3.z, acc.z))));
                    acc.w = fmaf(x.x, w0.w, fmaf(x.y, w1.w, fmaf(x.z, w2.w, fmaf(x.w, w3.w, acc.w))));
                }
                *(float4*)(sP + kg * ND + j4) = acc;
            }
            BAR256();
            if (t < ND) {
                float v = q1v;
#pragma unroll
                for (int g = 0; g < 8; g++) v += sP[g * ND + t];
                sH[t] = tanhf(v);
            }
            BAR256();

            // ---- B: up = h @ W2 + b2 ----
            {
                float4 acc = {0.f, 0.f, 0.f, 0.f};
                const float4* xr = (const float4*)(sH + kg * 16);
#pragma unroll
                for (int k4 = 0; k4 < 4; k4++) {
                    const float4 x = xr[k4];
                    const float* wb = sW2 + (kg * 16 + k4 * 4) * ND + j4;
                    const float4 w0 = *(const float4*)(wb);
                    const float4 w1 = *(const float4*)(wb + ND);
                    const float4 w2 = *(const float4*)(wb + 2 * ND);
                    const float4 w3 = *(const float4*)(wb + 3 * ND);
                    acc.x = fmaf(x.x, w0.x, fmaf(x.y, w1.x, fmaf(x.z, w2.x, fmaf(x.w, w3.x, acc.x))));
                    acc.y = fmaf(x.x, w0.y, fmaf(x.y, w1.y, fmaf(x.z, w2.y, fmaf(x.w, w3.y, acc.y))));
                    acc.z = fmaf(x.x, w0.z, fmaf(x.y, w1.z, fmaf(x.z, w2.z, fmaf(x.w, w3.z, acc.z))));
                    acc.w = fmaf(x.x, w0.w, fmaf(x.y, w1.w, fmaf(x.z, w2.w, fmaf(x.w, w3.w, acc.w))));
                }
                *(float4*)(sP + kg * ND + j4) = acc;
            }
            BAR256();
            if (t < ND) {
                float v = b2r;
#pragma unroll
                for (int g = 0; g < 8; g++) v += sP[g * ND + t];
                sUp[t] = v;
            }
            BAR256();

            // ---- C: e/a pre-activations via packed f32x2 FMA ----
            {
                unsigned long long acc01 = 0ull, acc23 = 0ull;
                const float4* xr = (const float4*)(sUp + ks * 32);
#pragma unroll
                for (int k4 = 0; k4 < 8; k4++) {
                    const float4 x = xr[k4];
                    unsigned long long xd;
                    DUP2(xd, x.x);
                    FMA2(acc01, ea2[(k4 * 4 + 0) * 2],     xd, acc01);
                    FMA2(acc23, ea2[(k4 * 4 + 0) * 2 + 1], xd, acc23);
                    DUP2(xd, x.y);
                    FMA2(acc01, ea2[(k4 * 4 + 1) * 2],     xd, acc01);
                    FMA2(acc23, ea2[(k4 * 4 + 1) * 2 + 1], xd, acc23);
                    DUP2(xd, x.z);
                    FMA2(acc01, ea2[(k4 * 4 + 2) * 2],     xd, acc01);
                    FMA2(acc23, ea2[(k4 * 4 + 2) * 2 + 1], xd, acc23);
                    DUP2(xd, x.w);
                    FMA2(acc01, ea2[(k4 * 4 + 3) * 2],     xd, acc01);
                    FMA2(acc23, ea2[(k4 * 4 + 3) * 2 + 1], xd, acc23);
                }
                float2 p01 = *(float2*)&acc01;
                float2 p23 = *(float2*)&acc23;
                float4 o = {p01.x, p01.y, p23.x, p23.y};
                *(float4*)(sP + ks * 256 + jq * 4) = o;
            }
            BAR256();
            {
                float v = biasO;
#pragma unroll
                for (int g = 0; g < 4; g++) v += sP[g * 256 + t];
                if (t < ND) sm[SM_E + par * ND + t]        = 1.f / (1.f + __expf(-v));
                else        sm[SM_A + par * ND + (t - ND)] = tanhf(v);
            }
        } else {
            // ---- mem warps: apply update s-1, produce r0/g/c for step s+1 ----
            const float* wu  = sAttn + (s ? (s - 1) * NM : 0);   // update weights
            const float* wsr = sAttn + s * NM;                    // for g, c
            const float* wr  = sAttn + ((s + 1 < NS) ? (s + 1) : (NS - 1)) * NM;  // for r0
            const float2 e2 = *(const float2*)(sm + SM_E + parm * ND + 2 * u);
            const float2 a2 = *(const float2*)(sm + SM_A + parm * ND + 2 * u);
            const float nex = -e2.x, ney = -e2.y;
            float2 r0v = {0.f, 0.f}, gv = {0.f, 0.f};
            float cacc = 0.f;
#pragma unroll
            for (int mq = 0; mq < NM / 2; mq++) {
                const float2 wuv = *(const float2*)(wu  + 2 * mq);
                const float2 wsv = *(const float2*)(wsr + 2 * mq);
                const float2 wrv = *(const float2*)(wr  + 2 * mq);
                {
                    float2 v = v2[2 * mq];
                    const float fx = fmaf(nex, v.x, a2.x);
                    const float fy = fmaf(ney, v.y, a2.y);
                    v.x = fmaf(wuv.x, fx, v.x);
                    v.y = fmaf(wuv.x, fy, v.y);
                    v2[2 * mq] = v;
                    const float px = wrv.x * v.x, py = wrv.x * v.y;
                    r0v.x += px; r0v.y += py;
                    gv.x = fmaf(wsv.x, px, gv.x);
                    gv.y = fmaf(wsv.x, py, gv.y);
                }
                {
                    float2 v = v2[2 * mq + 1];
                    const float fx = fmaf(nex, v.x, a2.x);
                    const float fy = fmaf(ney, v.y, a2.y);
                    v.x = fmaf(wuv.y, fx, v.x);
                    v.y = fmaf(wuv.y, fy, v.y);
                    v2[2 * mq + 1] = v;
                    const float px = wrv.y * v.x, py = wrv.y * v.y;
                    r0v.x += px; r0v.y += py;
                    gv.x = fmaf(wsv.y, px, gv.x);
                    gv.y = fmaf(wsv.y, py, gv.y);
                }
                cacc = fmaf(wrv.x, wsv.x, fmaf(wrv.y, wsv.y, cacc));
            }
            *(float2*)(sm + SM_R0 + parm * ND + 2 * u) = r0v;
            *(float2*)(sm + SM_G  + parm * ND + 2 * u) = gv;
            if (u == 0) sm[SM_C + parm] = cacc;
        }
        __syncthreads();
    }

    // ---- tail: read_out = w_99 . v_100 via the same identity (par=0, ea par=1) ----
    if (t < ND) {
        const float e  = sm[SM_E  + ND + t];
        const float a  = sm[SM_A  + ND + t];
        const float r0 = sm[SM_R0 + t];
        const float gg = sm[SM_G  + t];
        const float cc = sm[SM_C];
        sRead[t] = fmaf(cc, a, fmaf(-e, gg, r0));
        const int qi = qseq[b * NS + (NS - 1)];
        sUp[t] = emb[qi * ND + t];   // qe_last
    }
    __syncthreads();

    // ---- output head ----
    if (t < 256) {
        const float* pin = (kg < 4) ? sRead : (sUp - ND);
        float4 acc = {0.f, 0.f, 0.f, 0.f};
#pragma unroll
        for (int i = 0; i < 32; i++) {
            const int k = kg * 32 + i;
            const float x = pin[k];
            const float4 w = *(const float4*)(out_w1 + k * ND + j4);
            acc.x = fmaf(x, w.x, acc.x);
            acc.y = fmaf(x, w.y, acc.y);
            acc.z = fmaf(x, w.z, acc.z);
            acc.w = fmaf(x, w.w, acc.w);
        }
        *(float4*)(sP + kg * ND + j4) = acc;
    }
    __syncthreads();
    if (t < ND) {
        float v = out_b1[t];
#pragma unroll
        for (int g = 0; g < 8; g++) v += sP[g * ND + t];
        sH[t] = fmaxf(v, 0.f) * out_w2[t];
    }
    __syncthreads();
    if (t < 32) {
        float v = sH[t] + sH[t + 32] + sH[t + 64] + sH[t + 96];
#pragma unroll
        for (int o = 16; o; o >>= 1) v += __shfl_xor_sync(0xffffffffu, v, o);
        if (t == 0) out[b] = 1.f / (1.f + __expf(-(v + out_b2[0])));
    }
}

// ---------------------------------------------------------------------------
extern "C" void kernel_launch(void* const* d_in, const int* in_sizes, int n_in,
                              void* d_out, int out_size) {
    const int*   qseq   = (const int*)  d_in[0];
    // d_in[1] = answer_seq (unused by reference)
    const float* emb    = (const float*)d_in[2];
    const float* keym   = (const float*)d_in[3];
    const float* vu_w1  = (const float*)d_in[4];
    const float* vu_b1  = (const float*)d_in[5];
    const float* vu_w2  = (const float*)d_in[6];
    const float* vu_b2  = (const float*)d_in[7];
    const float* er_w   = (const float*)d_in[8];
    const float* er_b   = (const float*)d_in[9];
    const float* ad_w   = (const float*)d_in[10];
    const float* ad_b   = (const float*)d_in[11];
    const float* out_w1 = (const float*)d_in[12];
    const float* out_b1 = (const float*)d_in[13];
    const float* out_w2 = (const float*)d_in[14];
    const float* out_b2 = (const float*)d_in[15];
    float* out = (float*)d_out;

    cudaFuncSetAttribute(precompute_kernel,
                         cudaFuncAttributeMaxDynamicSharedMemorySize, PRE_SMEM_BYTES);
    cudaFuncSetAttribute(recurrent_kernel,
                         cudaFuncAttributeMaxDynamicSharedMemorySize, SMEM_BYTES);

    precompute_kernel<<<NROW / RPB, 256, PRE_SMEM_BYTES>>>(qseq, emb, keym, vu_w1, vu_b1);
    recurrent_kernel<<<NB, T, SMEM_BYTES>>>(qseq, emb, vu_w1, vu_w2, vu_b2,
                                            er_w, er_b, ad_w, ad_b,
                                            out_w1, out_b1, out_w2, out_b2, out);
}

// round 6
// speedup vs baseline: 1.2286x; 1.2286x over previous
#include <cuda_runtime.h>
#include <cstdint>
#include <math.h>

#define NB 128   // batch
#define NS 100   // seq len
#define NM 50    // memory slots
#define ND 128   // dim
#define T  320   // threads: 256 compute + 64 mem

#define NROW (NB * NS)     // 12800 (b,s) rows
#define RPB  32            // rows per precompute block
#define KS   132           // padded key row stride

// Scratch for precomputed attention weights and qe@W1b+b1
__device__ float g_attn[NB * NS * NM];
__device__ float g_q1[NB * NS * ND];

// packed fp32x2 helpers (sm_100+)
#define PACK2(d, xx, yy) asm("mov.b64 %0, {%1, %2};" : "=l"(d) : "r"(__float_as_uint(xx)), "r"(__float_as_uint(yy)))
#define DUP2(d, xx)      asm("mov.b64 %0, {%1, %1};" : "=l"(d) : "r"(__float_as_uint(xx)))
#define FMA2(d, a, b, c) asm("fma.rn.f32x2 %0, %1, %2, %3;" : "=l"(d) : "l"(a), "l"(b), "l"(c))
#define BAR256()         asm volatile("bar.sync 1, 256;" ::: "memory")

// ---------------------------------------------------------------------------
// K1: tiled batched precompute (unchanged, ~4us)
// ---------------------------------------------------------------------------
#define P_KEY  0
#define P_W1B  (NM * KS)
#define P_QE   (P_W1B + ND * ND)
#define P_B1   (P_QE + RPB * ND)
#define P_IDS  (P_B1 + ND)
#define P_TOTF (P_IDS + RPB)
#define PRE_SMEM_BYTES (P_TOTF * 4)

__global__ __launch_bounds__(256, 1)
void precompute_kernel(const int* __restrict__ qseq,
                       const float* __restrict__ emb,
                       const float* __restrict__ keym,
                       const float* __restrict__ vu_w1,
                       const float* __restrict__ vu_b1) {
    extern __shared__ float ps[];
    float* sKey = ps + P_KEY;
    float* sW1b = ps + P_W1B;
    float* sQe  = ps + P_QE;
    float* sB1  = ps + P_B1;
    int*   sIds = (int*)(ps + P_IDS);

    const int t  = threadIdx.x;
    const int r0 = blockIdx.x * RPB;

    if (t < RPB) sIds[t] = qseq[r0 + t];

    for (int i = t; i < NM * ND / 4; i += 256) {
        const int m = i / 32, c4 = i % 32;
        *(float4*)(sKey + m * KS + c4 * 4) = ((const float4*)keym)[i];
    }
    {
        const float4* src = (const float4*)(vu_w1 + ND * ND);
        for (int i = t; i < ND * ND / 4; i += 256) ((float4*)sW1b)[i] = src[i];
    }
    if (t < ND) sB1[t] = vu_b1[t];
    __syncthreads();

    for (int i = t; i < RPB * 32; i += 256) {
        const int row = i >> 5, c4 = i & 31;
        const float4* src = (const float4*)(emb + (size_t)sIds[row] * ND);
        *(float4*)(sQe + row * ND + c4 * 4) = src[c4];
    }
    __syncthreads();

    {
        const int wid = t >> 5, lid = t & 31;
        const int mB = (lid < NM - 32) ? lid + 32 : lid;
        float acc0[4] = {0, 0, 0, 0}, acc1[4] = {0, 0, 0, 0};
        const float* kA = sKey + lid * KS;
        const float* kB = sKey + mB * KS;
#pragma unroll
        for (int k4 = 0; k4 < 32; k4++) {
            const float4 a = *(const float4*)(kA + k4 * 4);
            const float4 b = *(const float4*)(kB + k4 * 4);
#pragma unroll
            for (int r = 0; r < 4; r++) {
                const float4 q = *(const float4*)(sQe + (wid * 4 + r) * ND + k4 * 4);
                acc0[r] = fmaf(q.x, a.x, fmaf(q.y, a.y, fmaf(q.z, a.z, fmaf(q.w, a.w, acc0[r]))));
                acc1[r] = fmaf(q.x, b.x, fmaf(q.y, b.y, fmaf(q.z, b.z, fmaf(q.w, b.w, acc1[r]))));
            }
        }
        const bool hasB = (lid < NM - 32);
#pragma unroll
        for (int r = 0; r < 4; r++) {
            float v0 = acc0[r];
            float v1 = hasB ? acc1[r] : -1e30f;
            float mx = fmaxf(v0, v1);
#pragma unroll
            for (int o = 16; o; o >>= 1) mx = fmaxf(mx, __shfl_xor_sync(0xffffffffu, mx, o));
            float e0 = __expf(v0 - mx);
            float e1 = hasB ? __expf(v1 - mx) : 0.f;
            float sum = e0 + e1;
#pragma unroll
            for (int o = 16; o; o >>= 1) sum += __shfl_xor_sync(0xffffffffu, sum, o);
            const float inv = 1.f / sum;
            float* dst = g_attn + (size_t)(r0 + wid * 4 + r) * NM;
            dst[lid] = e0 * inv;
            if (hasB) dst[lid + 32] = e1 * inv;
        }
    }

    {
        const int cg = t & 31;
        const int rg = t >> 5;
        float4 acc[4] = {{0,0,0,0},{0,0,0,0},{0,0,0,0},{0,0,0,0}};
#pragma unroll 8
        for (int k4 = 0; k4 < 32; k4++) {
            const float4 w0 = *(const float4*)(sW1b + (k4 * 4 + 0) * ND + cg * 4);
            const float4 w1 = *(const float4*)(sW1b + (k4 * 4 + 1) * ND + cg * 4);
            const float4 w2 = *(const float4*)(sW1b + (k4 * 4 + 2) * ND + cg * 4);
            const float4 w3 = *(const float4*)(sW1b + (k4 * 4 + 3) * ND + cg * 4);
#pragma unroll
            for (int r = 0; r < 4; r++) {
                const float4 q = *(const float4*)(sQe + (rg * 4 + r) * ND + k4 * 4);
                acc[r].x = fmaf(q.x, w0.x, fmaf(q.y, w1.x, fmaf(q.z, w2.x, fmaf(q.w, w3.x, acc[r].x))));
                acc[r].y = fmaf(q.x, w0.y, fmaf(q.y, w1.y, fmaf(q.z, w2.y, fmaf(q.w, w3.y, acc[r].y))));
                acc[r].z = fmaf(q.x, w0.z, fmaf(q.y, w1.z, fmaf(q.z, w2.z, fmaf(q.w, w3.z, acc[r].z))));
                acc[r].w = fmaf(q.x, w0.w, fmaf(q.y, w1.w, fmaf(q.z, w2.w, fmaf(q.w, w3.w, acc[r].w))));
            }
        }
        const float4 b4 = *(const float4*)(sB1 + cg * 4);
#pragma unroll
        for (int r = 0; r < 4; r++) {
            float4 o = acc[r];
            o.x += b4.x; o.y += b4.y; o.z += b4.z; o.w += b4.w;
            *(float4*)(g_q1 + (size_t)(r0 + rg * 4 + r) * ND + cg * 4) = o;
        }
    }
}

// ---------------------------------------------------------------------------
// K2: warp-specialized recurrent kernel. v state now in SMEM (no reg spill).
//  threads 0..255  : compute warps — read-combine, A, B, C chain
//  threads 256..319: mem warps — update v (step s-1) and produce r0/g/c for
//                    step s+1, overlapped with compute.
// Identity: read_{s} = r0 - e_{s-1}.g + c*a_{s-1},
//   r0 = w_s . v_{s-1},  g = sum_m w_s[m] w_{s-1}[m] v_{s-1}[m][:],
//   c  = sum_m w_s[m] w_{s-1}[m]   (with v already updated through step s-2).
// ---------------------------------------------------------------------------
// smem layout (floats)
#define SM_W1   0
#define SM_W2   16384
#define SM_ATTN 32768          // 100*50 = 5000
#define SM_P    37768          // 1024 scratch
#define SM_READ 38792          // 128
#define SM_H    38920          // 128
#define SM_UP   39048          // 128
#define SM_E    39176          // 2 x 128 (parity)
#define SM_A    39432          // 2 x 128
#define SM_R0   39688          // 2 x 128
#define SM_G    39944          // 2 x 128
#define SM_C    40200          // 2 (+2 pad)
#define SM_V    40204          // 50*128 = 6400
#define SM_TOTF (SM_V + NM * ND)
#define SMEM_BYTES (SM_TOTF * 4)

__global__ __launch_bounds__(T, 1)
void recurrent_kernel(const int* __restrict__ qseq,
                      const float* __restrict__ emb,
                      const float* __restrict__ vu_w1,
                      const float* __restrict__ vu_w2,
                      const float* __restrict__ vu_b2,
                      const float* __restrict__ er_w,
                      const float* __restrict__ er_b,
                      const float* __restrict__ ad_w,
                      const float* __restrict__ ad_b,
                      const float* __restrict__ out_w1,
                      const float* __restrict__ out_b1,
                      const float* __restrict__ out_w2,
                      const float* __restrict__ out_b2,
                      float* __restrict__ out) {
    extern __shared__ float sm[];
    float* sW1   = sm + SM_W1;
    float* sW2   = sm + SM_W2;
    float* sAttn = sm + SM_ATTN;
    float* sP    = sm + SM_P;
    float* sRead = sm + SM_READ;
    float* sH    = sm + SM_H;
    float* sUp   = sm + SM_UP;
    float* sV    = sm + SM_V;

    const int b = blockIdx.x;
    const int t = threadIdx.x;

    // ---- shared init ----
    for (int i = t; i < ND * ND; i += T) { sW1[i] = vu_w1[i]; sW2[i] = vu_w2[i]; }
    for (int i = t; i < NS * NM; i += T) sAttn[i] = g_attn[b * NS * NM + i];
    for (int i = t; i < 2 * ND * 4 + 4; i += T) sm[SM_E + i] = 0.f;  // e/a/r0/g/c
    for (int i = t; i < NM * ND; i += T) sV[i] = 0.f;

    // ---- compute-role register state: er/ad weights packed f32x2 ----
    const int jq = t & 63;
    const int ks = (t >> 6) & 3;
    unsigned long long ea2[64];
    float biasO = 0.f, b2r = 0.f;
    if (t < 256) {
        const float* src = (jq < 32) ? (er_w + jq * 4) : (ad_w + (jq - 32) * 4);
#pragma unroll
        for (int kk = 0; kk < 32; kk++) {
            const float4 w4 = *(const float4*)(src + (ks * 32 + kk) * ND);
            PACK2(ea2[kk * 2],     w4.x, w4.y);
            PACK2(ea2[kk * 2 + 1], w4.z, w4.w);
        }
        if (t < ND) { biasO = er_b[t]; b2r = vu_b2[t]; }
        else        { biasO = ad_b[t - ND]; }
    }
    const int u = t - 256;         // 0..63 for mem threads

    // compute stage mappings
    const int j4 = (t & 31) * 4;
    const int kg = (t >> 5) & 7;

    __syncthreads();

    const float* q1b = g_q1 + b * NS * ND;

    for (int s = 0; s < NS; s++) {
        const int par  = s & 1;         // r0/g/c consumed this step; e/a written this step
        const int parm = (s + 1) & 1;   // e/a from previous step; r0/g/c written for next

        if (t < 256) {
            // prefetch q1 (consumed in A-reduce)
            float q1v = 0.f;
            if (t < ND) q1v = q1b[s * ND + t];

            // ---- R: read_s = r0 - e.g + c*a ----
            if (t < ND) {
                const float e  = sm[SM_E  + parm * ND + t];
                const float a  = sm[SM_A  + parm * ND + t];
                const float r0 = sm[SM_R0 + par  * ND + t];
                const float gg = sm[SM_G  + par  * ND + t];
                const float cc = sm[SM_C  + par];
                sRead[t] = fmaf(cc, a, fmaf(-e, gg, r0));
            }
            BAR256();

            // ---- A: h = tanh(read @ W1a + q1) ----
            {
                float4 acc = {0.f, 0.f, 0.f, 0.f};
                const float4* xr = (const float4*)(sRead + kg * 16);
#pragma unroll
                for (int k4 = 0; k4 < 4; k4++) {
                    const float4 x = xr[k4];
                    const float* wb = sW1 + (kg * 16 + k4 * 4) * ND + j4;
                    const float4 w0 = *(const float4*)(wb);
                    const float4 w1 = *(const float4*)(wb + ND);
                    const float4 w2 = *(const float4*)(wb + 2 * ND);
                    const float4 w3 = *(const float4*)(wb + 3 * ND);
                    acc.x = fmaf(x.x, w0.x, fmaf(x.y, w1.x, fmaf(x.z, w2.x, fmaf(x.w, w3.x, acc.x))));
                    acc.y = fmaf(x.x, w0.y, fmaf(x.y, w1.y, fmaf(x.z, w2.y, fmaf(x.w, w3.y, acc.y))));
                    acc.z = fmaf(x.x, w0.z, fmaf(x.y, w1.z, fmaf(x.z, w2.z, fmaf(x.w, w3.z, acc.z))));
                    acc.w = fmaf(x.x, w0.w, fmaf(x.y, w1.w, fmaf(x.z, w2.w, fmaf(x.w, w3.w, acc.w))));
                }
                *(float4*)(sP + kg * ND + j4) = acc;
            }
            BAR256();
            if (t < ND) {
                float v = q1v;
#pragma unroll
                for (int g = 0; g < 8; g++) v += sP[g * ND + t];
                sH[t] = tanhf(v);
            }
            BAR256();

            // ---- B: up = h @ W2 + b2 ----
            {
                float4 acc = {0.f, 0.f, 0.f, 0.f};
                const float4* xr = (const float4*)(sH + kg * 16);
#pragma unroll
                for (int k4 = 0; k4 < 4; k4++) {
                    const float4 x = xr[k4];
                    const float* wb = sW2 + (kg * 16 + k4 * 4) * ND + j4;
                    const float4 w0 = *(const float4*)(wb);
                    const float4 w1 = *(const float4*)(wb + ND);
                    const float4 w2 = *(const float4*)(wb + 2 * ND);
                    const float4 w3 = *(const float4*)(wb + 3 * ND);
                    acc.x = fmaf(x.x, w0.x, fmaf(x.y, w1.x, fmaf(x.z, w2.x, fmaf(x.w, w3.x, acc.x))));
                    acc.y = fmaf(x.x, w0.y, fmaf(x.y, w1.y, fmaf(x.z, w2.y, fmaf(x.w, w3.y, acc.y))));
                    acc.z = fmaf(x.x, w0.z, fmaf(x.y, w1.z, fmaf(x.z, w2.z, fmaf(x.w, w3.z, acc.z))));
                    acc.w = fmaf(x.x, w0.w, fmaf(x.y, w1.w, fmaf(x.z, w2.w, fmaf(x.w, w3.w, acc.w))));
                }
                *(float4*)(sP + kg * ND + j4) = acc;
            }
            BAR256();
            if (t < ND) {
                float v = b2r;
#pragma unroll
                for (int g = 0; g < 8; g++) v += sP[g * ND + t];
                sUp[t] = v;
            }
            BAR256();

            // ---- C: e/a pre-activations via packed f32x2 FMA ----
            {
                unsigned long long acc01 = 0ull, acc23 = 0ull;
                const float4* xr = (const float4*)(sUp + ks * 32);
#pragma unroll
                for (int k4 = 0; k4 < 8; k4++) {
                    const float4 x = xr[k4];
                    unsigned long long xd;
                    DUP2(xd, x.x);
                    FMA2(acc01, ea2[(k4 * 4 + 0) * 2],     xd, acc01);
                    FMA2(acc23, ea2[(k4 * 4 + 0) * 2 + 1], xd, acc23);
                    DUP2(xd, x.y);
                    FMA2(acc01, ea2[(k4 * 4 + 1) * 2],     xd, acc01);
                    FMA2(acc23, ea2[(k4 * 4 + 1) * 2 + 1], xd, acc23);
                    DUP2(xd, x.z);
                    FMA2(acc01, ea2[(k4 * 4 + 2) * 2],     xd, acc01);
                    FMA2(acc23, ea2[(k4 * 4 + 2) * 2 + 1], xd, acc23);
                    DUP2(xd, x.w);
                    FMA2(acc01, ea2[(k4 * 4 + 3) * 2],     xd, acc01);
                    FMA2(acc23, ea2[(k4 * 4 + 3) * 2 + 1], xd, acc23);
                }
                float2 p01 = *(float2*)&acc01;
                float2 p23 = *(float2*)&acc23;
                float4 o = {p01.x, p01.y, p23.x, p23.y};
                *(float4*)(sP + ks * 256 + jq * 4) = o;
            }
            BAR256();
            {
                float v = biasO;
#pragma unroll
                for (int g = 0; g < 4; g++) v += sP[g * 256 + t];
                if (t < ND) sm[SM_E + par * ND + t]        = 1.f / (1.f + __expf(-v));
                else        sm[SM_A + par * ND + (t - ND)] = tanhf(v);
            }
        } else {
            // ---- mem warps: apply update s-1 to sV, produce r0/g/c for s+1 ----
            const float* wu  = sAttn + (s ? (s - 1) * NM : 0);
            const float* wsr = sAttn + s * NM;
            const float* wr  = sAttn + ((s + 1 < NS) ? (s + 1) : (NS - 1)) * NM;
            const float2 e2 = *(const float2*)(sm + SM_E + parm * ND + 2 * u);
            const float2 a2 = *(const float2*)(sm + SM_A + parm * ND + 2 * u);
            const float nex = -e2.x, ney = -e2.y;
            float2 r0v = {0.f, 0.f}, gv = {0.f, 0.f};
            float cacc = 0.f;
#pragma unroll 5
            for (int m = 0; m < NM; m++) {
                const float wum = wu[m];
                const float wsm = wsr[m];
                const float wrm = wr[m];
                float2 v = *(float2*)(sV + m * ND + 2 * u);
                const float fx = fmaf(nex, v.x, a2.x);
                const float fy = fmaf(ney, v.y, a2.y);
                v.x = fmaf(wum, fx, v.x);
                v.y = fmaf(wum, fy, v.y);
                *(float2*)(sV + m * ND + 2 * u) = v;
                const float px = wrm * v.x, py = wrm * v.y;
                r0v.x += px; r0v.y += py;
                gv.x = fmaf(wsm, px, gv.x);
                gv.y = fmaf(wsm, py, gv.y);
                cacc = fmaf(wrm, wsm, cacc);
            }
            *(float2*)(sm + SM_R0 + parm * ND + 2 * u) = r0v;
            *(float2*)(sm + SM_G  + parm * ND + 2 * u) = gv;
            if (u == 0) sm[SM_C + parm] = cacc;
        }
        __syncthreads();
    }

    // ---- tail: read_out = w_99 . v_100 via the same identity ----
    if (t < ND) {
        const float e  = sm[SM_E  + ND + t];
        const float a  = sm[SM_A  + ND + t];
        const float r0 = sm[SM_R0 + t];
        const float gg = sm[SM_G  + t];
        const float cc = sm[SM_C];
        sRead[t] = fmaf(cc, a, fmaf(-e, gg, r0));
        const int qi = qseq[b * NS + (NS - 1)];
        sUp[t] = emb[qi * ND + t];   // qe_last
    }
    __syncthreads();

    // ---- output head ----
    if (t < 256) {
        const float* pin = (kg < 4) ? sRead : (sUp - ND);
        float4 acc = {0.f, 0.f, 0.f, 0.f};
#pragma unroll
        for (int i = 0; i < 32; i++) {
            const int k = kg * 32 + i;
            const float x = pin[k];
            const float4 w = *(const float4*)(out_w1 + k * ND + j4);
            acc.x = fmaf(x, w.x, acc.x);
            acc.y = fmaf(x, w.y, acc.y);
            acc.z = fmaf(x, w.z, acc.z);
            acc.w = fmaf(x, w.w, acc.w);
        }
        *(float4*)(sP + kg * ND + j4) = acc;
    }
    __syncthreads();
    if (t < ND) {
        float v = out_b1[t];
#pragma unroll
        for (int g = 0; g < 8; g++) v += sP[g * ND + t];
        sH[t] = fmaxf(v, 0.f) * out_w2[t];
    }
    __syncthreads();
    if (t < 32) {
        float v = sH[t] + sH[t + 32] + sH[t + 64] + sH[t + 96];
#pragma unroll
        for (int o = 16; o; o >>= 1) v += __shfl_xor_sync(0xffffffffu, v, o);
        if (t == 0) out[b] = 1.f / (1.f + __expf(-(v + out_b2[0])));
    }
}

// ---------------------------------------------------------------------------
extern "C" void kernel_launch(void* const* d_in, const int* in_sizes, int n_in,
                              void* d_out, int out_size) {
    const int*   qseq   = (const int*)  d_in[0];
    // d_in[1] = answer_seq (unused by reference)
    const float* emb    = (const float*)d_in[2];
    const float* keym   = (const float*)d_in[3];
    const float* vu_w1  = (const float*)d_in[4];
    const float* vu_b1  = (const float*)d_in[5];
    const float* vu_w2  = (const float*)d_in[6];
    const float* vu_b2  = (const float*)d_in[7];
    const float* er_w   = (const float*)d_in[8];
    const float* er_b   = (const float*)d_in[9];
    const float* ad_w   = (const float*)d_in[10];
    const float* ad_b   = (const float*)d_in[11];
    const float* out_w1 = (const float*)d_in[12];
    const float* out_b1 = (const float*)d_in[13];
    const float* out_w2 = (const float*)d_in[14];
    const float* out_b2 = (const float*)d_in[15];
    float* out = (float*)d_out;

    cudaFuncSetAttribute(precompute_kernel,
                         cudaFuncAttributeMaxDynamicSharedMemorySize, PRE_SMEM_BYTES);
    cudaFuncSetAttribute(recurrent_kernel,
                         cudaFuncAttributeMaxDynamicSharedMemorySize, SMEM_BYTES);

    precompute_kernel<<<NROW / RPB, 256, PRE_SMEM_BYTES>>>(qseq, emb, keym, vu_w1, vu_b1);
    recurrent_kernel<<<NB, T, SMEM_BYTES>>>(qseq, emb, vu_w1, vu_w2, vu_b2,
                                            er_b ? er_w : er_w, er_b, ad_w, ad_b,
                                            out_w1, out_b1, out_w2, out_b2, out);
}

// round 8
// speedup vs baseline: 1.5434x; 1.2563x over previous
#include <cuda_runtime.h>
#include <cuda_fp16.h>
#include <cstdint>
#include <math.h>

#define NB 128   // batch
#define NS 100   // seq len
#define NM 50    // memory slots
#define ND 128   // dim
#define T  384   // threads: 256 compute + 128 mem

#define NROW (NB * NS)     // 12800 (b,s) rows
#define RPB  32            // rows per precompute block
#define KS   132           // padded key row stride

// Scratch for precomputed attention weights and qe@W1b+b1
__device__ float g_attn[NB * NS * NM];
__device__ float g_q1[NB * NS * ND];

// packed fp32x2 helpers (sm_100+)
#define PACK2(d, xx, yy) asm("mov.b64 %0, {%1, %2};" : "=l"(d) : "r"(__float_as_uint(xx)), "r"(__float_as_uint(yy)))
#define DUP2(d, xx)      asm("mov.b64 %0, {%1, %1};" : "=l"(d) : "r"(__float_as_uint(xx)))
#define FMA2(d, a, b, c) asm("fma.rn.f32x2 %0, %1, %2, %3;" : "=l"(d) : "l"(a), "l"(b), "l"(c))
#define BAR256()         asm volatile("bar.sync 1, 256;" ::: "memory")

// ---------------------------------------------------------------------------
// K1: tiled batched precompute (unchanged, ~4us)
// ---------------------------------------------------------------------------
#define P_KEY  0
#define P_W1B  (NM * KS)
#define P_QE   (P_W1B + ND * ND)
#define P_B1   (P_QE + RPB * ND)
#define P_IDS  (P_B1 + ND)
#define P_TOTF (P_IDS + RPB)
#define PRE_SMEM_BYTES (P_TOTF * 4)

__global__ __launch_bounds__(256, 1)
void precompute_kernel(const int* __restrict__ qseq,
                       const float* __restrict__ emb,
                       const float* __restrict__ keym,
                       const float* __restrict__ vu_w1,
                       const float* __restrict__ vu_b1) {
    extern __shared__ float ps[];
    float* sKey = ps + P_KEY;
    float* sW1b = ps + P_W1B;
    float* sQe  = ps + P_QE;
    float* sB1  = ps + P_B1;
    int*   sIds = (int*)(ps + P_IDS);

    const int t  = threadIdx.x;
    const int r0 = blockIdx.x * RPB;

    if (t < RPB) sIds[t] = qseq[r0 + t];

    for (int i = t; i < NM * ND / 4; i += 256) {
        const int m = i / 32, c4 = i % 32;
        *(float4*)(sKey + m * KS + c4 * 4) = ((const float4*)keym)[i];
    }
    {
        const float4* src = (const float4*)(vu_w1 + ND * ND);
        for (int i = t; i < ND * ND / 4; i += 256) ((float4*)sW1b)[i] = src[i];
    }
    if (t < ND) sB1[t] = vu_b1[t];
    __syncthreads();

    for (int i = t; i < RPB * 32; i += 256) {
        const int row = i >> 5, c4 = i & 31;
        const float4* src = (const float4*)(emb + (size_t)sIds[row] * ND);
        *(float4*)(sQe + row * ND + c4 * 4) = src[c4];
    }
    __syncthreads();

    {
        const int wid = t >> 5, lid = t & 31;
        const int mB = (lid < NM - 32) ? lid + 32 : lid;
        float acc0[4] = {0, 0, 0, 0}, acc1[4] = {0, 0, 0, 0};
        const float* kA = sKey + lid * KS;
        const float* kB = sKey + mB * KS;
#pragma unroll
        for (int k4 = 0; k4 < 32; k4++) {
            const float4 a = *(const float4*)(kA + k4 * 4);
            const float4 b = *(const float4*)(kB + k4 * 4);
#pragma unroll
            for (int r = 0; r < 4; r++) {
                const float4 q = *(const float4*)(sQe + (wid * 4 + r) * ND + k4 * 4);
                acc0[r] = fmaf(q.x, a.x, fmaf(q.y, a.y, fmaf(q.z, a.z, fmaf(q.w, a.w, acc0[r]))));
                acc1[r] = fmaf(q.x, b.x, fmaf(q.y, b.y, fmaf(q.z, b.z, fmaf(q.w, b.w, acc1[r]))));
            }
        }
        const bool hasB = (lid < NM - 32);
#pragma unroll
        for (int r = 0; r < 4; r++) {
            float v0 = acc0[r];
            float v1 = hasB ? acc1[r] : -1e30f;
            float mx = fmaxf(v0, v1);
#pragma unroll
            for (int o = 16; o; o >>= 1) mx = fmaxf(mx, __shfl_xor_sync(0xffffffffu, mx, o));
            float e0 = __expf(v0 - mx);
            float e1 = hasB ? __expf(v1 - mx) : 0.f;
            float sum = e0 + e1;
#pragma unroll
            for (int o = 16; o; o >>= 1) sum += __shfl_xor_sync(0xffffffffu, sum, o);
            const float inv = 1.f / sum;
            float* dst = g_attn + (size_t)(r0 + wid * 4 + r) * NM;
            dst[lid] = e0 * inv;
            if (hasB) dst[lid + 32] = e1 * inv;
        }
    }

    {
        const int cg = t & 31;
        const int rg = t >> 5;
        float4 acc[4] = {{0,0,0,0},{0,0,0,0},{0,0,0,0},{0,0,0,0}};
#pragma unroll 8
        for (int k4 = 0; k4 < 32; k4++) {
            const float4 w0 = *(const float4*)(sW1b + (k4 * 4 + 0) * ND + cg * 4);
            const float4 w1 = *(const float4*)(sW1b + (k4 * 4 + 1) * ND + cg * 4);
            const float4 w2 = *(const float4*)(sW1b + (k4 * 4 + 2) * ND + cg * 4);
            const float4 w3 = *(const float4*)(sW1b + (k4 * 4 + 3) * ND + cg * 4);
#pragma unroll
            for (int r = 0; r < 4; r++) {
                const float4 q = *(const float4*)(sQe + (rg * 4 + r) * ND + k4 * 4);
                acc[r].x = fmaf(q.x, w0.x, fmaf(q.y, w1.x, fmaf(q.z, w2.x, fmaf(q.w, w3.x, acc[r].x))));
                acc[r].y = fmaf(q.x, w0.y, fmaf(q.y, w1.y, fmaf(q.z, w2.y, fmaf(q.w, w3.y, acc[r].y))));
                acc[r].z = fmaf(q.x, w0.z, fmaf(q.y, w1.z, fmaf(q.z, w2.z, fmaf(q.w, w3.z, acc[r].z))));
                acc[r].w = fmaf(q.x, w0.w, fmaf(q.y, w1.w, fmaf(q.z, w2.w, fmaf(q.w, w3.w, acc[r].w))));
            }
        }
        const float4 b4 = *(const float4*)(sB1 + cg * 4);
#pragma unroll
        for (int r = 0; r < 4; r++) {
            float4 o = acc[r];
            o.x += b4.x; o.y += b4.y; o.z += b4.z; o.w += b4.w;
            *(float4*)(g_q1 + (size_t)(r0 + rg * 4 + r) * ND + cg * 4) = o;
        }
    }
}

// ---------------------------------------------------------------------------
// K2: warp-specialized recurrent kernel, fp16 weight storage for W1a/W2
// (math in fp32), 8 compute warps + 4 mem warps (balanced 3 warps/SMSP).
// Identity: read_{s} = r0 - e_{s-1}.g + c*a_{s-1}  (see R5/R6).
// ---------------------------------------------------------------------------
// smem layout (floats)
#define SM_W1H  0                         // 128*128 half = 8192 floats
#define SM_W2H  8192                      // 8192 floats
#define SM_ATTN 16384                     // 100*50 = 5000
#define SM_P    21384                     // 1024 scratch
#define SM_READ 22408                     // 128
#define SM_H    22536                     // 128
#define SM_UP   22664                     // 128
#define SM_E    22792                     // 2 x 128 (parity)
#define SM_A    23048                     // 2 x 128
#define SM_R0   23304                     // 2 x 128
#define SM_G    23560                     // 2 x 128
#define SM_C    23816                     // 2 (+2 pad)
#define SM_V    23820                     // 50*128 = 6400
#define SM_TOTF (SM_V + NM * ND)
#define SMEM_BYTES (SM_TOTF * 4)

__global__ __launch_bounds__(T, 1)
void recurrent_kernel(const int* __restrict__ qseq,
                      const float* __restrict__ emb,
                      const float* __restrict__ vu_w1,
                      const float* __restrict__ vu_w2,
                      const float* __restrict__ vu_b2,
                      const float* __restrict__ er_w,
                      const float* __restrict__ er_b,
                      const float* __restrict__ ad_w,
                      const float* __restrict__ ad_b,
                      const float* __restrict__ out_w1,
                      const float* __restrict__ out_b1,
                      const float* __restrict__ out_w2,
                      const float* __restrict__ out_b2,
                      float* __restrict__ out) {
    extern __shared__ float sm[];
    __half* sW1h = (__half*)(sm + SM_W1H);
    __half* sW2h = (__half*)(sm + SM_W2H);
    float* sAttn = sm + SM_ATTN;
    float* sP    = sm + SM_P;
    float* sRead = sm + SM_READ;
    float* sH    = sm + SM_H;
    float* sUp   = sm + SM_UP;
    float* sV    = sm + SM_V;

    const int b = blockIdx.x;
    const int t = threadIdx.x;

    // ---- shared init ----
    for (int i = t; i < ND * ND; i += T) {
        sW1h[i] = __float2half_rn(vu_w1[i]);
        sW2h[i] = __float2half_rn(vu_w2[i]);
    }
    for (int i = t; i < NS * NM; i += T) sAttn[i] = g_attn[b * NS * NM + i];
    for (int i = t; i < 2 * ND * 4 + 4; i += T) sm[SM_E + i] = 0.f;  // e/a/r0/g/c
    for (int i = t; i < NM * ND; i += T) sV[i] = 0.f;

    // ---- compute-role register state: er/ad weights packed f32x2 ----
    const int jq = t & 63;
    const int ks = (t >> 6) & 3;
    unsigned long long ea2[64];
    float biasO = 0.f, b2r = 0.f;
    if (t < 256) {
        const float* src = (jq < 32) ? (er_w + jq * 4) : (ad_w + (jq - 32) * 4);
#pragma unroll
        for (int kk = 0; kk < 32; kk++) {
            const float4 w4 = *(const float4*)(src + (ks * 32 + kk) * ND);
            PACK2(ea2[kk * 2],     w4.x, w4.y);
            PACK2(ea2[kk * 2 + 1], w4.z, w4.w);
        }
        if (t < ND) { biasO = er_b[t]; b2r = vu_b2[t]; }
        else        { biasO = ad_b[t - ND]; }
    }
    const int u = t - 256;         // 0..127 for mem threads (one d-column each)

    // compute stage mappings
    const int j4 = (t & 31) * 4;
    const int kg = (t >> 5) & 7;

    __syncthreads();

    const float* q1b = g_q1 + b * NS * ND;

    for (int s = 0; s < NS; s++) {
        const int par  = s & 1;         // r0/g/c consumed this step; e/a written this step
        const int parm = (s + 1) & 1;   // e/a from previous step; r0/g/c written for next

        if (t < 256) {
            // prefetch q1 (consumed in A-reduce)
            float q1v = 0.f;
            if (t < ND) q1v = q1b[s * ND + t];

            // ---- R: read_s = r0 - e.g + c*a ----
            if (t < ND) {
                const float e  = sm[SM_E  + parm * ND + t];
                const float a  = sm[SM_A  + parm * ND + t];
                const float r0 = sm[SM_R0 + par  * ND + t];
                const float gg = sm[SM_G  + par  * ND + t];
                const float cc = sm[SM_C  + par];
                sRead[t] = fmaf(cc, a, fmaf(-e, gg, r0));
            }
            BAR256();

            // ---- A: h = tanh(read @ W1a + q1), fp16 weights ----
            {
                float4 acc = {0.f, 0.f, 0.f, 0.f};
                const float4* xr = (const float4*)(sRead + kg * 16);
                const __half* wrow = sW1h + (kg * 16) * ND + j4;
#pragma unroll
                for (int k4 = 0; k4 < 4; k4++) {
                    const float4 x = xr[k4];
#define AK(W, kk, xs) { \
    const uint2 raw = *(const uint2*)((W) + (k4 * 4 + (kk)) * ND); \
    const float2 f01 = __half22float2(*(const __half2*)&raw.x); \
    const float2 f23 = __half22float2(*(const __half2*)&raw.y); \
    acc.x = fmaf(xs, f01.x, acc.x); \
    acc.y = fmaf(xs, f01.y, acc.y); \
    acc.z = fmaf(xs, f23.x, acc.z); \
    acc.w = fmaf(xs, f23.y, acc.w); }
                    AK(wrow, 0, x.x) AK(wrow, 1, x.y) AK(wrow, 2, x.z) AK(wrow, 3, x.w)
                }
                *(float4*)(sP + kg * ND + j4) = acc;
            }
            BAR256();
            if (t < ND) {
                float v = q1v;
#pragma unroll
                for (int g = 0; g < 8; g++) v += sP[g * ND + t];
                sH[t] = tanhf(v);
            }
            BAR256();

            // ---- B: up = h @ W2 + b2, fp16 weights ----
            {
                float4 acc = {0.f, 0.f, 0.f, 0.f};
                const float4* xr = (const float4*)(sH + kg * 16);
                const __half* wrow = sW2h + (kg * 16) * ND + j4;
#pragma unroll
                for (int k4 = 0; k4 < 4; k4++) {
                    const float4 x = xr[k4];
                    AK(wrow, 0, x.x) AK(wrow, 1, x.y) AK(wrow, 2, x.z) AK(wrow, 3, x.w)
                }
                *(float4*)(sP + kg * ND + j4) = acc;
            }
            BAR256();
            if (t < ND) {
                float v = b2r;
#pragma unroll
                for (int g = 0; g < 8; g++) v += sP[g * ND + t];
                sUp[t] = v;
            }
            BAR256();

            // ---- C: e/a pre-activations via packed f32x2 FMA (exact fp32 regs) ----
            {
                unsigned long long acc01 = 0ull, acc23 = 0ull;
                const float4* xr = (const float4*)(sUp + ks * 32);
#pragma unroll
                for (int k4 = 0; k4 < 8; k4++) {
                    const float4 x = xr[k4];
                    unsigned long long xd;
                    DUP2(xd, x.x);
                    FMA2(acc01, ea2[(k4 * 4 + 0) * 2],     xd, acc01);
                    FMA2(acc23, ea2[(k4 * 4 + 0) * 2 + 1], xd, acc23);
                    DUP2(xd, x.y);
                    FMA2(acc01, ea2[(k4 * 4 + 1) * 2],     xd, acc01);
                    FMA2(acc23, ea2[(k4 * 4 + 1) * 2 + 1], xd, acc23);
                    DUP2(xd, x.z);
                    FMA2(acc01, ea2[(k4 * 4 + 2) * 2],     xd, acc01);
                    FMA2(acc23, ea2[(k4 * 4 + 2) * 2 + 1], xd, acc23);
                    DUP2(xd, x.w);
                    FMA2(acc01, ea2[(k4 * 4 + 3) * 2],     xd, acc01);
                    FMA2(acc23, ea2[(k4 * 4 + 3) * 2 + 1], xd, acc23);
                }
                float2 p01 = *(float2*)&acc01;
                float2 p23 = *(float2*)&acc23;
                float4 o = {p01.x, p01.y, p23.x, p23.y};
                *(float4*)(sP + ks * 256 + jq * 4) = o;
            }
            BAR256();
            {
                float v = biasO;
#pragma unroll
                for (int g = 0; g < 4; g++) v += sP[g * 256 + t];
                if (t < ND) sm[SM_E + par * ND + t]        = 1.f / (1.f + __expf(-v));
                else        sm[SM_A + par * ND + (t - ND)] = tanhf(v);
            }
        } else {
            // ---- mem warps (128 thr): apply update s-1 to sV, r0/g/c for s+1 ----
            const float* wu  = sAttn + (s ? (s - 1) * NM : 0);
            const float* wsr = sAttn + s * NM;
            const float* wr  = sAttn + ((s + 1 < NS) ? (s + 1) : (NS - 1)) * NM;
            const float e = sm[SM_E + parm * ND + u];
            const float a = sm[SM_A + parm * ND + u];
            const float ne = -e;
            float r0v = 0.f, gv = 0.f, cacc = 0.f;
#pragma unroll 5
            for (int m = 0; m < NM; m++) {
                const float wum = wu[m];
                const float wsm = wsr[m];
                const float wrm = wr[m];
                float v = sV[m * ND + u];
                v = fmaf(wum, fmaf(ne, v, a), v);
                sV[m * ND + u] = v;
                const float p = wrm * v;
                r0v += p;
                gv   = fmaf(wsm, p, gv);
                cacc = fmaf(wrm, wsm, cacc);
            }
            sm[SM_R0 + parm * ND + u] = r0v;
            sm[SM_G  + parm * ND + u] = gv;
            if (u == 0) sm[SM_C + parm] = cacc;
        }
        __syncthreads();
    }

    // ---- tail: read_out = w_99 . v_100 via the same identity ----
    if (t < ND) {
        const float e  = sm[SM_E  + ND + t];
        const float a  = sm[SM_A  + ND + t];
        const float r0 = sm[SM_R0 + t];
        const float gg = sm[SM_G  + t];
        const float cc = sm[SM_C];
        sRead[t] = fmaf(cc, a, fmaf(-e, gg, r0));
        const int qi = qseq[b * NS + (NS - 1)];
        sUp[t] = emb[qi * ND + t];   // qe_last
    }
    __syncthreads();

    // ---- output head (fp32 weights from global; one-shot) ----
    if (t < 256) {
        const float* pin = (kg < 4) ? sRead : (sUp - ND);
        float4 acc = {0.f, 0.f, 0.f, 0.f};
#pragma unroll
        for (int i = 0; i < 32; i++) {
            const int k = kg * 32 + i;
            const float x = pin[k];
            const float4 w = *(const float4*)(out_w1 + k * ND + j4);
            acc.x = fmaf(x, w.x, acc.x);
            acc.y = fmaf(x, w.y, acc.y);
            acc.z = fmaf(x, w.z, acc.z);
            acc.w = fmaf(x, w.w, acc.w);
        }
        *(float4*)(sP + kg * ND + j4) = acc;
    }
    __syncthreads();
    if (t < ND) {
        float v = out_b1[t];
#pragma unroll
        for (int g = 0; g < 8; g++) v += sP[g * ND + t];
        sH[t] = fmaxf(v, 0.f) * out_w2[t];
    }
    __syncthreads();
    if (t < 32) {
        float v = sH[t] + sH[t + 32] + sH[t + 64] + sH[t + 96];
#pragma unroll
        for (int o = 16; o; o >>= 1) v += __shfl_xor_sync(0xffffffffu, v, o);
        if (t == 0) out[b] = 1.f / (1.f + __expf(-(v + out_b2[0])));
    }
}

// ---------------------------------------------------------------------------
extern "C" void kernel_launch(void* const* d_in, const int* in_sizes, int n_in,
                              void* d_out, int out_size) {
    const int*   qseq   = (const int*)  d_in[0];
    // d_in[1] = answer_seq (unused by reference)
    const float* emb    = (const float*)d_in[2];
    const float* keym   = (const float*)d_in[3];
    const float* vu_w1  = (const float*)d_in[4];
    const float* vu_b1  = (const float*)d_in[5];
    const float* vu_w2  = (const float*)d_in[6];
    const float* vu_b2  = (const float*)d_in[7];
    const float* er_w   = (const float*)d_in[8];
    const float* er_b   = (const float*)d_in[9];
    const float* ad_w   = (const float*)d_in[10];
    const float* ad_b   = (const float*)d_in[11];
    const float* out_w1 = (const float*)d_in[12];
    const float* out_b1 = (const float*)d_in[13];
    const float* out_w2 = (const float*)d_in[14];
    const float* out_b2 = (const float*)d_in[15];
    float* out = (float*)d_out;

    cudaFuncSetAttribute(precompute_kernel,
                         cudaFuncAttributeMaxDynamicSharedMemorySize, PRE_SMEM_BYTES);
    cudaFuncSetAttribute(recurrent_kernel,
                         cudaFuncAttributeMaxDynamicSharedMemorySize, SMEM_BYTES);

    precompute_kernel<<<NROW / RPB, 256, PRE_SMEM_BYTES>>>(qseq, emb, keym, vu_w1, vu_b1);
    recurrent_kernel<<<NB, T, SMEM_BYTES>>>(qseq, emb, vu_w1, vu_w2, vu_b2,
                                            er_w, er_b, ad_w, ad_b,
                                            out_w1, out_b1, out_w2, out_b2, out);
}

// round 9
// speedup vs baseline: 1.7333x; 1.1231x over previous
#include <cuda_runtime.h>
#include <cuda_fp16.h>
#include <cstdint>
#include <math.h>

#define NB 128   // batch
#define NS 100   // seq len
#define NM 50    // memory slots
#define ND 128   // dim
#define T  384   // threads: 256 compute + 128 mem
#define AS 52    // padded attn row stride (floats, 16B-aligned rows)

#define NROW (NB * NS)     // 12800 (b,s) rows
#define RPB  32            // rows per precompute block
#define KS   132           // padded key row stride

// Scratch for precomputed attention weights and qe@W1b+b1
__device__ float g_attn[NB * NS * NM];
__device__ float g_q1[NB * NS * ND];

// packed fp32x2 helpers (sm_100+)
#define PACK2(d, xx, yy) asm("mov.b64 %0, {%1, %2};" : "=l"(d) : "r"(__float_as_uint(xx)), "r"(__float_as_uint(yy)))
#define DUP2(d, xx)      asm("mov.b64 %0, {%1, %1};" : "=l"(d) : "r"(__float_as_uint(xx)))
#define FMA2(d, a, b, c) asm("fma.rn.f32x2 %0, %1, %2, %3;" : "=l"(d) : "l"(a), "l"(b), "l"(c))
#define BAR256()         asm volatile("bar.sync 1, 256;" ::: "memory")

// ---------------------------------------------------------------------------
// K1: tiled batched precompute (unchanged, ~4us)
// ---------------------------------------------------------------------------
#define P_KEY  0
#define P_W1B  (NM * KS)
#define P_QE   (P_W1B + ND * ND)
#define P_B1   (P_QE + RPB * ND)
#define P_IDS  (P_B1 + ND)
#define P_TOTF (P_IDS + RPB)
#define PRE_SMEM_BYTES (P_TOTF * 4)

__global__ __launch_bounds__(256, 1)
void precompute_kernel(const int* __restrict__ qseq,
                       const float* __restrict__ emb,
                       const float* __restrict__ keym,
                       const float* __restrict__ vu_w1,
                       const float* __restrict__ vu_b1) {
    extern __shared__ float ps[];
    float* sKey = ps + P_KEY;
    float* sW1b = ps + P_W1B;
    float* sQe  = ps + P_QE;
    float* sB1  = ps + P_B1;
    int*   sIds = (int*)(ps + P_IDS);

    const int t  = threadIdx.x;
    const int r0 = blockIdx.x * RPB;

    if (t < RPB) sIds[t] = qseq[r0 + t];

    for (int i = t; i < NM * ND / 4; i += 256) {
        const int m = i / 32, c4 = i % 32;
        *(float4*)(sKey + m * KS + c4 * 4) = ((const float4*)keym)[i];
    }
    {
        const float4* src = (const float4*)(vu_w1 + ND * ND);
        for (int i = t; i < ND * ND / 4; i += 256) ((float4*)sW1b)[i] = src[i];
    }
    if (t < ND) sB1[t] = vu_b1[t];
    __syncthreads();

    for (int i = t; i < RPB * 32; i += 256) {
        const int row = i >> 5, c4 = i & 31;
        const float4* src = (const float4*)(emb + (size_t)sIds[row] * ND);
        *(float4*)(sQe + row * ND + c4 * 4) = src[c4];
    }
    __syncthreads();

    {
        const int wid = t >> 5, lid = t & 31;
        const int mB = (lid < NM - 32) ? lid + 32 : lid;
        float acc0[4] = {0, 0, 0, 0}, acc1[4] = {0, 0, 0, 0};
        const float* kA = sKey + lid * KS;
        const float* kB = sKey + mB * KS;
#pragma unroll
        for (int k4 = 0; k4 < 32; k4++) {
            const float4 a = *(const float4*)(kA + k4 * 4);
            const float4 b = *(const float4*)(kB + k4 * 4);
#pragma unroll
            for (int r = 0; r < 4; r++) {
                const float4 q = *(const float4*)(sQe + (wid * 4 + r) * ND + k4 * 4);
                acc0[r] = fmaf(q.x, a.x, fmaf(q.y, a.y, fmaf(q.z, a.z, fmaf(q.w, a.w, acc0[r]))));
                acc1[r] = fmaf(q.x, b.x, fmaf(q.y, b.y, fmaf(q.z, b.z, fmaf(q.w, b.w, acc1[r]))));
            }
        }
        const bool hasB = (lid < NM - 32);
#pragma unroll
        for (int r = 0; r < 4; r++) {
            float v0 = acc0[r];
            float v1 = hasB ? acc1[r] : -1e30f;
            float mx = fmaxf(v0, v1);
#pragma unroll
            for (int o = 16; o; o >>= 1) mx = fmaxf(mx, __shfl_xor_sync(0xffffffffu, mx, o));
            float e0 = __expf(v0 - mx);
            float e1 = hasB ? __expf(v1 - mx) : 0.f;
            float sum = e0 + e1;
#pragma unroll
            for (int o = 16; o; o >>= 1) sum += __shfl_xor_sync(0xffffffffu, sum, o);
            const float inv = 1.f / sum;
            float* dst = g_attn + (size_t)(r0 + wid * 4 + r) * NM;
            dst[lid] = e0 * inv;
            if (hasB) dst[lid + 32] = e1 * inv;
        }
    }

    {
        const int cg = t & 31;
        const int rg = t >> 5;
        float4 acc[4] = {{0,0,0,0},{0,0,0,0},{0,0,0,0},{0,0,0,0}};
#pragma unroll 8
        for (int k4 = 0; k4 < 32; k4++) {
            const float4 w0 = *(const float4*)(sW1b + (k4 * 4 + 0) * ND + cg * 4);
            const float4 w1 = *(const float4*)(sW1b + (k4 * 4 + 1) * ND + cg * 4);
            const float4 w2 = *(const float4*)(sW1b + (k4 * 4 + 2) * ND + cg * 4);
            const float4 w3 = *(const float4*)(sW1b + (k4 * 4 + 3) * ND + cg * 4);
#pragma unroll
            for (int r = 0; r < 4; r++) {
                const float4 q = *(const float4*)(sQe + (rg * 4 + r) * ND + k4 * 4);
                acc[r].x = fmaf(q.x, w0.x, fmaf(q.y, w1.x, fmaf(q.z, w2.x, fmaf(q.w, w3.x, acc[r].x))));
                acc[r].y = fmaf(q.x, w0.y, fmaf(q.y, w1.y, fmaf(q.z, w2.y, fmaf(q.w, w3.y, acc[r].y))));
                acc[r].z = fmaf(q.x, w0.z, fmaf(q.y, w1.z, fmaf(q.z, w2.z, fmaf(q.w, w3.z, acc[r].z))));
                acc[r].w = fmaf(q.x, w0.w, fmaf(q.y, w1.w, fmaf(q.z, w2.w, fmaf(q.w, w3.w, acc[r].w))));
            }
        }
        const float4 b4 = *(const float4*)(sB1 + cg * 4);
#pragma unroll
        for (int r = 0; r < 4; r++) {
            float4 o = acc[r];
            o.x += b4.x; o.y += b4.y; o.z += b4.z; o.w += b4.w;
            *(float4*)(g_q1 + (size_t)(r0 + rg * 4 + r) * ND + cg * 4) = o;
        }
    }
}

// ---------------------------------------------------------------------------
// K2: warp-specialized recurrent kernel, reduced-barrier pipeline.
// Compute warps fold the reduce of the previous stage into their own
// prologue (k-sliced across warps) and broadcast x via __shfl.
// Stage scratch is double-buffered (P0: A/C partials, P1: B partials).
// Barriers per step: 3x bar.sync(1,256) + 1x __syncthreads.
// ---------------------------------------------------------------------------
// smem layout (floats)
#define SM_W1H  0                         // 128*128 half = 8192 floats
#define SM_W2H  8192                      // 8192 floats
#define SM_ATTN 16384                     // 100*52 = 5200 (padded rows)
#define SM_P0   21584                     // 1024 scratch (A and C partials)
#define SM_P1   22608                     // 1024 scratch (B partials)
#define SM_READ 23632                     // 128 (tail only)
#define SM_H    23760                     // 128 (tail only)
#define SM_UP   23888                     // 128 (tail only)
#define SM_B2   24016                     // 128
#define SM_E    24144                     // 2 x 128 (parity)
#define SM_A    24400                     // 2 x 128
#define SM_R0   24656                     // 2 x 128
#define SM_G    24912                     // 2 x 128
#define SM_C    25168                     // 2 (+2 pad)
#define SM_V    25172                     // 50*128 = 6400
#define SM_TOTF (SM_V + NM * ND)
#define SMEM_BYTES (SM_TOTF * 4)

__global__ __launch_bounds__(T, 1)
void recurrent_kernel(const int* __restrict__ qseq,
                      const float* __restrict__ emb,
                      const float* __restrict__ vu_w1,
                      const float* __restrict__ vu_w2,
                      const float* __restrict__ vu_b2,
                      const float* __restrict__ er_w,
                      const float* __restrict__ er_b,
                      const float* __restrict__ ad_w,
                      const float* __restrict__ ad_b,
                      const float* __restrict__ out_w1,
                      const float* __restrict__ out_b1,
                      const float* __restrict__ out_w2,
                      const float* __restrict__ out_b2,
                      float* __restrict__ out) {
    extern __shared__ float sm[];
    __half* sW1h = (__half*)(sm + SM_W1H);
    __half* sW2h = (__half*)(sm + SM_W2H);
    float* sAttn = sm + SM_ATTN;
    float* sP0   = sm + SM_P0;
    float* sP1   = sm + SM_P1;
    float* sRead = sm + SM_READ;
    float* sH    = sm + SM_H;
    float* sUp   = sm + SM_UP;
    float* sV    = sm + SM_V;

    const int b = blockIdx.x;
    const int t = threadIdx.x;

    // ---- shared init ----
    for (int i = t; i < ND * ND; i += T) {
        sW1h[i] = __float2half_rn(vu_w1[i]);
        sW2h[i] = __float2half_rn(vu_w2[i]);
    }
    for (int i = t; i < NS * NM; i += T)
        sAttn[(i / NM) * AS + (i % NM)] = g_attn[b * NS * NM + i];
    for (int i = t; i < 2 * ND * 4 + 4; i += T) sm[SM_E + i] = 0.f;  // e/a/r0/g/c
    for (int i = t; i < NM * ND; i += T) sV[i] = 0.f;
    if (t < ND) sm[SM_B2 + t] = vu_b2[t];

    // ---- compute-role register state: er/ad weights packed f32x2 ----
    const int lid = t & 31;
    const int jq = t & 63;
    const int ks = (t >> 6) & 3;
    unsigned long long ea2[64];
    float biasO = 0.f;
    if (t < 256) {
        const float* src = (jq < 32) ? (er_w + jq * 4) : (ad_w + (jq - 32) * 4);
#pragma unroll
        for (int kk = 0; kk < 32; kk++) {
            const float4 w4 = *(const float4*)(src + (ks * 32 + kk) * ND);
            PACK2(ea2[kk * 2],     w4.x, w4.y);
            PACK2(ea2[kk * 2 + 1], w4.z, w4.w);
        }
        if (t < ND) biasO = er_b[t];
        else        biasO = ad_b[t - ND];
    }
    const int u = t - 256;         // 0..127 for mem threads (one d-column each)

    // compute stage mappings
    const int j4 = (t & 31) * 4;
    const int kg = (t >> 5) & 7;       // warp id for compute warps
    const int kownA = kg * 16 + (lid & 15);   // A/B prologue slice (16 k per warp)
    const int kownC = ks * 32 + lid;          // C prologue slice (32 k per warp pair)

    __syncthreads();

    const float* q1b = g_q1 + b * NS * ND;

    for (int s = 0; s < NS; s++) {
        const int par  = s & 1;         // r0/g/c consumed; e/a written this step
        const int parm = (s + 1) & 1;   // e/a from previous step; r0/g/c written for next

        if (t < 256) {
            // prefetch q1 for this warp's k-slice (consumed in B prologue)
            const float q1f = q1b[s * ND + kownA];

            // ---- A prologue: read[kownA] = r0 - e*g + c*a (per-lane) ----
            float rd;
            {
                const float e  = sm[SM_E  + parm * ND + kownA];
                const float a  = sm[SM_A  + parm * ND + kownA];
                const float r0 = sm[SM_R0 + par  * ND + kownA];
                const float gg = sm[SM_G  + par  * ND + kownA];
                const float cc = sm[SM_C  + par];
                rd = fmaf(cc, a, fmaf(-e, gg, r0));
            }
            // ---- A GEMV: partials over k-slice, x by shuffle ----
            {
                float4 acc = {0.f, 0.f, 0.f, 0.f};
                const __half* wrow = sW1h + (kg * 16) * ND + j4;
#pragma unroll
                for (int i = 0; i < 16; i++) {
                    const float xs = __shfl_sync(0xffffffffu, rd, i);
                    const uint2 raw = *(const uint2*)(wrow + i * ND);
                    const float2 f01 = __half22float2(*(const __half2*)&raw.x);
                    const float2 f23 = __half22float2(*(const __half2*)&raw.y);
                    acc.x = fmaf(xs, f01.x, acc.x);
                    acc.y = fmaf(xs, f01.y, acc.y);
                    acc.z = fmaf(xs, f23.x, acc.z);
                    acc.w = fmaf(xs, f23.y, acc.w);
                }
                *(float4*)(sP0 + kg * ND + j4) = acc;
            }
            BAR256();

            // ---- B prologue: h[kownA] = tanh(q1 + sum partials) ----
            float hv;
            {
                float v = q1f;
#pragma unroll
                for (int g = 0; g < 8; g++) v += sP0[g * ND + kownA];
                hv = tanhf(v);
            }
            // ---- B GEMV ----
            {
                float4 acc = {0.f, 0.f, 0.f, 0.f};
                const __half* wrow = sW2h + (kg * 16) * ND + j4;
#pragma unroll
                for (int i = 0; i < 16; i++) {
                    const float xs = __shfl_sync(0xffffffffu, hv, i);
                    const uint2 raw = *(const uint2*)(wrow + i * ND);
                    const float2 f01 = __half22float2(*(const __half2*)&raw.x);
                    const float2 f23 = __half22float2(*(const __half2*)&raw.y);
                    acc.x = fmaf(xs, f01.x, acc.x);
                    acc.y = fmaf(xs, f01.y, acc.y);
                    acc.z = fmaf(xs, f23.x, acc.z);
                    acc.w = fmaf(xs, f23.y, acc.w);
                }
                *(float4*)(sP1 + kg * ND + j4) = acc;
            }
            BAR256();

            // ---- C prologue: up[kownC] = b2 + sum partials ----
            float upv;
            {
                float v = sm[SM_B2 + kownC];
#pragma unroll
                for (int g = 0; g < 8; g++) v += sP1[g * ND + kownC];
                upv = v;
            }
            // ---- C GEMV: e/a pre-activations via packed f32x2 FMA ----
            {
                unsigned long long acc01 = 0ull, acc23 = 0ull;
#pragma unroll
                for (int i = 0; i < 32; i++) {
                    const float xs = __shfl_sync(0xffffffffu, upv, i);
                    unsigned long long xd;
                    DUP2(xd, xs);
                    FMA2(acc01, ea2[i * 2],     xd, acc01);
                    FMA2(acc23, ea2[i * 2 + 1], xd, acc23);
                }
                float2 p01 = *(float2*)&acc01;
                float2 p23 = *(float2*)&acc23;
                float4 o = {p01.x, p01.y, p23.x, p23.y};
                *(float4*)(sP0 + ks * 256 + jq * 4) = o;
            }
            BAR256();

            // ---- final: e = sigmoid(.), a = tanh(.) ----
            {
                float v = biasO;
#pragma unroll
                for (int g = 0; g < 4; g++) v += sP0[g * 256 + t];
                if (t < ND) sm[SM_E + par * ND + t]        = 1.f / (1.f + __expf(-v));
                else        sm[SM_A + par * ND + (t - ND)] = tanhf(v);
            }
        } else {
            // ---- mem warps (128 thr): apply update s-1 to sV, r0/g/c for s+1 ----
            const float* wu  = sAttn + (s ? (s - 1) * AS : 0);
            const float* wsr = sAttn + s * AS;
            const float* wr  = sAttn + ((s + 1 < NS) ? (s + 1) : (NS - 1)) * AS;
            const float e = sm[SM_E + parm * ND + u];
            const float a = sm[SM_A + parm * ND + u];
            const float ne = -e;
            float r0v = 0.f, gv = 0.f, cacc = 0.f;

#define MEMSTEP(wum, wsm, wrm, m) { \
    float v = sV[(m) * ND + u]; \
    v = fmaf(wum, fmaf(ne, v, a), v); \
    sV[(m) * ND + u] = v; \
    const float p = (wrm) * v; \
    r0v += p; \
    gv   = fmaf(wsm, p, gv); \
    cacc = fmaf(wrm, wsm, cacc); }

#pragma unroll
            for (int mq = 0; mq < 12; mq++) {
                const float4 wu4 = *(const float4*)(wu  + mq * 4);
                const float4 ws4 = *(const float4*)(wsr + mq * 4);
                const float4 wr4 = *(const float4*)(wr  + mq * 4);
                MEMSTEP(wu4.x, ws4.x, wr4.x, mq * 4 + 0)
                MEMSTEP(wu4.y, ws4.y, wr4.y, mq * 4 + 1)
                MEMSTEP(wu4.z, ws4.z, wr4.z, mq * 4 + 2)
                MEMSTEP(wu4.w, ws4.w, wr4.w, mq * 4 + 3)
            }
            {
                const float2 wu2 = *(const float2*)(wu  + 48);
                const float2 ws2 = *(const float2*)(wsr + 48);
                const float2 wr2 = *(const float2*)(wr  + 48);
                MEMSTEP(wu2.x, ws2.x, wr2.x, 48)
                MEMSTEP(wu2.y, ws2.y, wr2.y, 49)
            }
#undef MEMSTEP
            sm[SM_R0 + parm * ND + u] = r0v;
            sm[SM_G  + parm * ND + u] = gv;
            if (u == 0) sm[SM_C + parm] = cacc;
        }
        __syncthreads();
    }

    // ---- tail: read_out = w_99 . v_100 via the same identity ----
    if (t < ND) {
        const float e  = sm[SM_E  + ND + t];
        const float a  = sm[SM_A  + ND + t];
        const float r0 = sm[SM_R0 + t];
        const float gg = sm[SM_G  + t];
        const float cc = sm[SM_C];
        sRead[t] = fmaf(cc, a, fmaf(-e, gg, r0));
        const int qi = qseq[b * NS + (NS - 1)];
        sUp[t] = emb[qi * ND + t];   // qe_last
    }
    __syncthreads();

    // ---- output head (fp32 weights from global; one-shot) ----
    if (t < 256) {
        const float* pin = (kg < 4) ? sRead : (sUp - ND);
        float4 acc = {0.f, 0.f, 0.f, 0.f};
#pragma unroll
        for (int i = 0; i < 32; i++) {
            const int k = kg * 32 + i;
            const float x = pin[k];
            const float4 w = *(const float4*)(out_w1 + k * ND + j4);
            acc.x = fmaf(x, w.x, acc.x);
            acc.y = fmaf(x, w.y, acc.y);
            acc.z = fmaf(x, w.z, acc.z);
            acc.w = fmaf(x, w.w, acc.w);
        }
        *(float4*)(sP0 + kg * ND + j4) = acc;
    }
    __syncthreads();
    if (t < ND) {
        float v = out_b1[t];
#pragma unroll
        for (int g = 0; g < 8; g++) v += sP0[g * ND + t];
        sH[t] = fmaxf(v, 0.f) * out_w2[t];
    }
    __syncthreads();
    if (t < 32) {
        float v = sH[t] + sH[t + 32] + sH[t + 64] + sH[t + 96];
#pragma unroll
        for (int o = 16; o; o >>= 1) v += __shfl_xor_sync(0xffffffffu, v, o);
        if (t == 0) out[b] = 1.f / (1.f + __expf(-(v + out_b2[0])));
    }
}

// ---------------------------------------------------------------------------
extern "C" void kernel_launch(void* const* d_in, const int* in_sizes, int n_in,
                              void* d_out, int out_size) {
    const int*   qseq   = (const int*)  d_in[0];
    // d_in[1] = answer_seq (unused by reference)
    const float* emb    = (const float*)d_in[2];
    const float* keym   = (const float*)d_in[3];
    const float* vu_w1  = (const float*)d_in[4];
    const float* vu_b1  = (const float*)d_in[5];
    const float* vu_w2  = (const float*)d_in[6];
    const float* vu_b2  = (const float*)d_in[7];
    const float* er_w   = (const float*)d_in[8];
    const float* er_b   = (const float*)d_in[9];
    const float* ad_w   = (const float*)d_in[10];
    const float* ad_b   = (const float*)d_in[11];
    const float* out_w1 = (const float*)d_in[12];
    const float* out_b1 = (const float*)d_in[13];
    const float* out_w2 = (const float*)d_in[14];
    const float* out_b2 = (const float*)d_in[15];
    float* out = (float*)d_out;

    cudaFuncSetAttribute(precompute_kernel,
                         cudaFuncAttributeMaxDynamicSharedMemorySize, PRE_SMEM_BYTES);
    cudaFuncSetAttribute(recurrent_kernel,
                         cudaFuncAttributeMaxDynamicSharedMemorySize, SMEM_BYTES);

    precompute_kernel<<<NROW / RPB, 256, PRE_SMEM_BYTES>>>(qseq, emb, keym, vu_w1, vu_b1);
    recurrent_kernel<<<NB, T, SMEM_BYTES>>>(qseq, emb, vu_w1, vu_w2, vu_b2,
                                            er_w, er_b, ad_w, ad_b,
                                            out_w1, out_b1, out_w2, out_b2, out);
}

// round 10
// speedup vs baseline: 1.7336x; 1.0002x over previous
#include <cuda_runtime.h>
#include <cuda_fp16.h>
#include <cstdint>
#include <math.h>

#define NB 128   // batch
#define NS 100   // seq len
#define NM 50    // memory slots
#define ND 128   // dim
#define T  384   // threads: 256 compute + 128 mem
#define AS 52    // padded attn row stride (floats, 16B-aligned rows)

#define NROW (NB * NS)     // 12800 (b,s) rows
#define RPB  32            // rows per precompute block
#define KS   132           // padded key row stride

// Scratch for precomputed attention weights and qe@W1b+b1
__device__ float g_attn[NB * NS * NM];
__device__ float g_q1[NB * NS * ND];

// packed fp32x2 helpers (sm_100+)
#define PACK2(d, xx, yy) asm("mov.b64 %0, {%1, %2};" : "=l"(d) : "r"(__float_as_uint(xx)), "r"(__float_as_uint(yy)))
#define DUP2(d, xx)      asm("mov.b64 %0, {%1, %1};" : "=l"(d) : "r"(__float_as_uint(xx)))
#define FMA2(d, a, b, c) asm("fma.rn.f32x2 %0, %1, %2, %3;" : "=l"(d) : "l"(a), "l"(b), "l"(c))
#define BAR256()         asm volatile("bar.sync 1, 256;" ::: "memory")

__device__ __forceinline__ float tanh_fast(float x) {
    float y;
    asm("tanh.approx.f32 %0, %1;" : "=f"(y) : "f"(x));
    return y;
}
__device__ __forceinline__ float sigmoid_fast(float x) {
    return fmaf(0.5f, tanh_fast(0.5f * x), 0.5f);
}

// ---------------------------------------------------------------------------
// K1: tiled batched precompute (unchanged, ~4us)
// ---------------------------------------------------------------------------
#define P_KEY  0
#define P_W1B  (NM * KS)
#define P_QE   (P_W1B + ND * ND)
#define P_B1   (P_QE + RPB * ND)
#define P_IDS  (P_B1 + ND)
#define P_TOTF (P_IDS + RPB)
#define PRE_SMEM_BYTES (P_TOTF * 4)

__global__ __launch_bounds__(256, 1)
void precompute_kernel(const int* __restrict__ qseq,
                       const float* __restrict__ emb,
                       const float* __restrict__ keym,
                       const float* __restrict__ vu_w1,
                       const float* __restrict__ vu_b1) {
    extern __shared__ float ps[];
    float* sKey = ps + P_KEY;
    float* sW1b = ps + P_W1B;
    float* sQe  = ps + P_QE;
    float* sB1  = ps + P_B1;
    int*   sIds = (int*)(ps + P_IDS);

    const int t  = threadIdx.x;
    const int r0 = blockIdx.x * RPB;

    if (t < RPB) sIds[t] = qseq[r0 + t];

    for (int i = t; i < NM * ND / 4; i += 256) {
        const int m = i / 32, c4 = i % 32;
        *(float4*)(sKey + m * KS + c4 * 4) = ((const float4*)keym)[i];
    }
    {
        const float4* src = (const float4*)(vu_w1 + ND * ND);
        for (int i = t; i < ND * ND / 4; i += 256) ((float4*)sW1b)[i] = src[i];
    }
    if (t < ND) sB1[t] = vu_b1[t];
    __syncthreads();

    for (int i = t; i < RPB * 32; i += 256) {
        const int row = i >> 5, c4 = i & 31;
        const float4* src = (const float4*)(emb + (size_t)sIds[row] * ND);
        *(float4*)(sQe + row * ND + c4 * 4) = src[c4];
    }
    __syncthreads();

    {
        const int wid = t >> 5, lid = t & 31;
        const int mB = (lid < NM - 32) ? lid + 32 : lid;
        float acc0[4] = {0, 0, 0, 0}, acc1[4] = {0, 0, 0, 0};
        const float* kA = sKey + lid * KS;
        const float* kB = sKey + mB * KS;
#pragma unroll
        for (int k4 = 0; k4 < 32; k4++) {
            const float4 a = *(const float4*)(kA + k4 * 4);
            const float4 b = *(const float4*)(kB + k4 * 4);
#pragma unroll
            for (int r = 0; r < 4; r++) {
                const float4 q = *(const float4*)(sQe + (wid * 4 + r) * ND + k4 * 4);
                acc0[r] = fmaf(q.x, a.x, fmaf(q.y, a.y, fmaf(q.z, a.z, fmaf(q.w, a.w, acc0[r]))));
                acc1[r] = fmaf(q.x, b.x, fmaf(q.y, b.y, fmaf(q.z, b.z, fmaf(q.w, b.w, acc1[r]))));
            }
        }
        const bool hasB = (lid < NM - 32);
#pragma unroll
        for (int r = 0; r < 4; r++) {
            float v0 = acc0[r];
            float v1 = hasB ? acc1[r] : -1e30f;
            float mx = fmaxf(v0, v1);
#pragma unroll
            for (int o = 16; o; o >>= 1) mx = fmaxf(mx, __shfl_xor_sync(0xffffffffu, mx, o));
            float e0 = __expf(v0 - mx);
            float e1 = hasB ? __expf(v1 - mx) : 0.f;
            float sum = e0 + e1;
#pragma unroll
            for (int o = 16; o; o >>= 1) sum += __shfl_xor_sync(0xffffffffu, sum, o);
            const float inv = 1.f / sum;
            float* dst = g_attn + (size_t)(r0 + wid * 4 + r) * NM;
            dst[lid] = e0 * inv;
            if (hasB) dst[lid + 32] = e1 * inv;
        }
    }

    {
        const int cg = t & 31;
        const int rg = t >> 5;
        float4 acc[4] = {{0,0,0,0},{0,0,0,0},{0,0,0,0},{0,0,0,0}};
#pragma unroll 8
        for (int k4 = 0; k4 < 32; k4++) {
            const float4 w0 = *(const float4*)(sW1b + (k4 * 4 + 0) * ND + cg * 4);
            const float4 w1 = *(const float4*)(sW1b + (k4 * 4 + 1) * ND + cg * 4);
            const float4 w2 = *(const float4*)(sW1b + (k4 * 4 + 2) * ND + cg * 4);
            const float4 w3 = *(const float4*)(sW1b + (k4 * 4 + 3) * ND + cg * 4);
#pragma unroll
            for (int r = 0; r < 4; r++) {
                const float4 q = *(const float4*)(sQe + (rg * 4 + r) * ND + k4 * 4);
                acc[r].x = fmaf(q.x, w0.x, fmaf(q.y, w1.x, fmaf(q.z, w2.x, fmaf(q.w, w3.x, acc[r].x))));
                acc[r].y = fmaf(q.x, w0.y, fmaf(q.y, w1.y, fmaf(q.z, w2.y, fmaf(q.w, w3.y, acc[r].y))));
                acc[r].z = fmaf(q.x, w0.z, fmaf(q.y, w1.z, fmaf(q.z, w2.z, fmaf(q.w, w3.z, acc[r].z))));
                acc[r].w = fmaf(q.x, w0.w, fmaf(q.y, w1.w, fmaf(q.z, w2.w, fmaf(q.w, w3.w, acc[r].w))));
            }
        }
        const float4 b4 = *(const float4*)(sB1 + cg * 4);
#pragma unroll
        for (int r = 0; r < 4; r++) {
            float4 o = acc[r];
            o.x += b4.x; o.y += b4.y; o.z += b4.z; o.w += b4.w;
            *(float4*)(g_q1 + (size_t)(r0 + rg * 4 + r) * ND + cg * 4) = o;
        }
    }
}

// ---------------------------------------------------------------------------
// K2: warp-specialized recurrent kernel, activation folded into consumers.
// Per step: A-pro(+act) A-GEMV BAR B-pro B-GEMV BAR C-pro C-GEMV syncthreads.
// C pre-activation partials are parity-double-buffered in sPC; consumers
// (next-step A-prologue lanes, mem warps) apply bias + sigmoid/tanh locally.
// ---------------------------------------------------------------------------
// smem layout (floats)
#define SM_W1H  0                         // 128*128 half = 8192 floats
#define SM_W2H  8192                      // 8192 floats
#define SM_ATTN 16384                     // 100*52 = 5200 (padded rows)
#define SM_PA   21584                     // 1024 (A partials)
#define SM_PB   22608                     // 1024 (B partials)
#define SM_PC   23632                     // 2 x 1024 (C pre-act partials, parity)
#define SM_READ 25680                     // 128 (tail only)
#define SM_H    25808                     // 128 (tail only)
#define SM_UP   25936                     // 128 (tail only)
#define SM_B2   26064                     // 128
#define SM_BE   26192                     // 128 (er_b)
#define SM_BA   26320                     // 128 (ad_b)
#define SM_R0   26448                     // 2 x 128 (parity)
#define SM_G    26704                     // 2 x 128
#define SM_C    26960                     // 2 (+2 pad)
#define SM_V    26964                     // 50*128 = 6400
#define SM_TOTF (SM_V + NM * ND)
#define SMEM_BYTES (SM_TOTF * 4)

__global__ __launch_bounds__(T, 1)
void recurrent_kernel(const int* __restrict__ qseq,
                      const float* __restrict__ emb,
                      const float* __restrict__ vu_w1,
                      const float* __restrict__ vu_w2,
                      const float* __restrict__ vu_b2,
                      const float* __restrict__ er_w,
                      const float* __restrict__ er_b,
                      const float* __restrict__ ad_w,
                      const float* __restrict__ ad_b,
                      const float* __restrict__ out_w1,
                      const float* __restrict__ out_b1,
                      const float* __restrict__ out_w2,
                      const float* __restrict__ out_b2,
                      float* __restrict__ out) {
    extern __shared__ float sm[];
    __half* sW1h = (__half*)(sm + SM_W1H);
    __half* sW2h = (__half*)(sm + SM_W2H);
    float* sAttn = sm + SM_ATTN;
    float* sPA   = sm + SM_PA;
    float* sPB   = sm + SM_PB;
    float* sPC   = sm + SM_PC;
    float* sRead = sm + SM_READ;
    float* sH    = sm + SM_H;
    float* sUp   = sm + SM_UP;
    float* sV    = sm + SM_V;

    const int b = blockIdx.x;
    const int t = threadIdx.x;

    // ---- shared init ----
    for (int i = t; i < ND * ND; i += T) {
        sW1h[i] = __float2half_rn(vu_w1[i]);
        sW2h[i] = __float2half_rn(vu_w2[i]);
    }
    for (int i = t; i < NS * NM; i += T)
        sAttn[(i / NM) * AS + (i % NM)] = g_attn[b * NS * NM + i];
    for (int i = t; i < 2 * 1024; i += T) sPC[i] = 0.f;
    for (int i = t; i < 2 * ND * 2 + 4; i += T) sm[SM_R0 + i] = 0.f;  // r0/g/c
    for (int i = t; i < NM * ND; i += T) sV[i] = 0.f;
    if (t < ND) {
        sm[SM_B2 + t] = vu_b2[t];
        sm[SM_BE + t] = er_b[t];
        sm[SM_BA + t] = ad_b[t];
    }

    // ---- compute-role register state: er/ad weights packed f32x2 ----
    const int lid = t & 31;
    const int jq = t & 63;
    const int ks = (t >> 6) & 3;
    unsigned long long ea2[64];
    if (t < 256) {
        const float* src = (jq < 32) ? (er_w + jq * 4) : (ad_w + (jq - 32) * 4);
#pragma unroll
        for (int kk = 0; kk < 32; kk++) {
            const float4 w4 = *(const float4*)(src + (ks * 32 + kk) * ND);
            PACK2(ea2[kk * 2],     w4.x, w4.y);
            PACK2(ea2[kk * 2 + 1], w4.z, w4.w);
        }
    }
    const int u = t - 256;         // 0..127 for mem threads (one d-column each)

    // compute stage mappings
    const int j4 = (t & 31) * 4;
    const int kg = (t >> 5) & 7;       // warp id for compute warps
    const int kownA = kg * 16 + (lid & 15);   // A/B prologue slice (16 k per warp)
    const int kownC = ks * 32 + lid;          // C prologue slice

    __syncthreads();

    const float* q1b = g_q1 + b * NS * ND;

    for (int s = 0; s < NS; s++) {
        const int par  = s & 1;         // sPC written this step; r0/g/c consumed
        const int parm = (s + 1) & 1;   // sPC from previous step; r0/g/c written

        if (t < 256) {
            // prefetch q1 for this warp's k-slice (consumed in B prologue)
            const float q1f = q1b[s * ND + kownA];
            const float* pc = sPC + parm * 1024;

            // ---- A prologue: reconstruct e/a at kownA, then read value ----
            float rd;
            {
                float pe = sm[SM_BE + kownA];
                float pa = sm[SM_BA + kownA];
#pragma unroll
                for (int g = 0; g < 4; g++) {
                    pe += pc[g * 256 + kownA];
                    pa += pc[g * 256 + 128 + kownA];
                }
                const float e = sigmoid_fast(pe);
                const float a = tanh_fast(pa);
                const float r0 = sm[SM_R0 + par * ND + kownA];
                const float gg = sm[SM_G  + par * ND + kownA];
                const float cc = sm[SM_C  + par];
                rd = fmaf(cc, a, fmaf(-e, gg, r0));
            }
            // ---- A GEMV: partials over k-slice, x by shuffle ----
            {
                float4 acc = {0.f, 0.f, 0.f, 0.f};
                const __half* wrow = sW1h + (kg * 16) * ND + j4;
#pragma unroll
                for (int i = 0; i < 16; i++) {
                    const float xs = __shfl_sync(0xffffffffu, rd, i);
                    const uint2 raw = *(const uint2*)(wrow + i * ND);
                    const float2 f01 = __half22float2(*(const __half2*)&raw.x);
                    const float2 f23 = __half22float2(*(const __half2*)&raw.y);
                    acc.x = fmaf(xs, f01.x, acc.x);
                    acc.y = fmaf(xs, f01.y, acc.y);
                    acc.z = fmaf(xs, f23.x, acc.z);
                    acc.w = fmaf(xs, f23.y, acc.w);
                }
                *(float4*)(sPA + kg * ND + j4) = acc;
            }
            BAR256();

            // ---- B prologue: h[kownA] = tanh(q1 + sum partials) ----
            float hv;
            {
                float v = q1f;
#pragma unroll
                for (int g = 0; g < 8; g++) v += sPA[g * ND + kownA];
                hv = tanh_fast(v);
            }
            // ---- B GEMV ----
            {
                float4 acc = {0.f, 0.f, 0.f, 0.f};
                const __half* wrow = sW2h + (kg * 16) * ND + j4;
#pragma unroll
                for (int i = 0; i < 16; i++) {
                    const float xs = __shfl_sync(0xffffffffu, hv, i);
                    const uint2 raw = *(const uint2*)(wrow + i * ND);
                    const float2 f01 = __half22float2(*(const __half2*)&raw.x);
                    const float2 f23 = __half22float2(*(const __half2*)&raw.y);
                    acc.x = fmaf(xs, f01.x, acc.x);
                    acc.y = fmaf(xs, f01.y, acc.y);
                    acc.z = fmaf(xs, f23.x, acc.z);
                    acc.w = fmaf(xs, f23.y, acc.w);
                }
                *(float4*)(sPB + kg * ND + j4) = acc;
            }
            BAR256();

            // ---- C prologue: up[kownC] = b2 + sum partials ----
            float upv;
            {
                float v = sm[SM_B2 + kownC];
#pragma unroll
                for (int g = 0; g < 8; g++) v += sPB[g * ND + kownC];
                upv = v;
            }
            // ---- C GEMV: e/a pre-activation partials via packed f32x2 FMA ----
            {
                unsigned long long acc01 = 0ull, acc23 = 0ull;
#pragma unroll
                for (int i = 0; i < 32; i++) {
                    const float xs = __shfl_sync(0xffffffffu, upv, i);
                    unsigned long long xd;
                    DUP2(xd, xs);
                    FMA2(acc01, ea2[i * 2],     xd, acc01);
                    FMA2(acc23, ea2[i * 2 + 1], xd, acc23);
                }
                float2 p01 = *(float2*)&acc01;
                float2 p23 = *(float2*)&acc23;
                float4 o = {p01.x, p01.y, p23.x, p23.y};
                *(float4*)(sPC + par * 1024 + ks * 256 + jq * 4) = o;
            }
        } else {
            // ---- mem warps: reconstruct e/a at u, update sV, r0/g/c for s+1 ----
            const float* wu  = sAttn + (s ? (s - 1) * AS : 0);
            const float* wsr = sAttn + s * AS;
            const float* wr  = sAttn + ((s + 1 < NS) ? (s + 1) : (NS - 1)) * AS;
            float e, a;
            if (s == 0) {
                e = 0.f; a = 0.f;   // v=0: step-0 "update" must be a no-op
            } else {
                const float* pc = sPC + parm * 1024;
                float pe = sm[SM_BE + u];
                float pa = sm[SM_BA + u];
#pragma unroll
                for (int g = 0; g < 4; g++) {
                    pe += pc[g * 256 + u];
                    pa += pc[g * 256 + 128 + u];
                }
                e = sigmoid_fast(pe);
                a = tanh_fast(pa);
            }
            const float ne = -e;
            float r0v = 0.f, gv = 0.f, cacc = 0.f;

#define MEMSTEP(wum, wsm, wrm, m) { \
    float v = sV[(m) * ND + u]; \
    v = fmaf(wum, fmaf(ne, v, a), v); \
    sV[(m) * ND + u] = v; \
    const float p = (wrm) * v; \
    r0v += p; \
    gv   = fmaf(wsm, p, gv); \
    cacc = fmaf(wrm, wsm, cacc); }

#pragma unroll
            for (int mq = 0; mq < 12; mq++) {
                const float4 wu4 = *(const float4*)(wu  + mq * 4);
                const float4 ws4 = *(const float4*)(wsr + mq * 4);
                const float4 wr4 = *(const float4*)(wr  + mq * 4);
                MEMSTEP(wu4.x, ws4.x, wr4.x, mq * 4 + 0)
                MEMSTEP(wu4.y, ws4.y, wr4.y, mq * 4 + 1)
                MEMSTEP(wu4.z, ws4.z, wr4.z, mq * 4 + 2)
                MEMSTEP(wu4.w, ws4.w, wr4.w, mq * 4 + 3)
            }
            {
                const float2 wu2 = *(const float2*)(wu  + 48);
                const float2 ws2 = *(const float2*)(wsr + 48);
                const float2 wr2 = *(const float2*)(wr  + 48);
                MEMSTEP(wu2.x, ws2.x, wr2.x, 48)
                MEMSTEP(wu2.y, ws2.y, wr2.y, 49)
            }
#undef MEMSTEP
            sm[SM_R0 + parm * ND + u] = r0v;
            sm[SM_G  + parm * ND + u] = gv;
            if (u == 0) sm[SM_C + parm] = cacc;
        }
        __syncthreads();
    }

    // ---- tail: read_out = w_99 . v_100 via the same identity ----
    if (t < ND) {
        const float* pc = sPC + 1024;       // parity of s=99
        float pe = sm[SM_BE + t];
        float pa = sm[SM_BA + t];
#pragma unroll
        for (int g = 0; g < 4; g++) {
            pe += pc[g * 256 + t];
            pa += pc[g * 256 + 128 + t];
        }
        const float e = sigmoid_fast(pe);
        const float a = tanh_fast(pa);
        const float r0 = sm[SM_R0 + t];     // parity 0 (written at s=99)
        const float gg = sm[SM_G  + t];
        const float cc = sm[SM_C];
        sRead[t] = fmaf(cc, a, fmaf(-e, gg, r0));
        const int qi = qseq[b * NS + (NS - 1)];
        sUp[t] = emb[qi * ND + t];   // qe_last
    }
    __syncthreads();

    // ---- output head (fp32 weights from global; one-shot) ----
    if (t < 256) {
        const float* pin = (kg < 4) ? sRead : (sUp - ND);
        float4 acc = {0.f, 0.f, 0.f, 0.f};
#pragma unroll
        for (int i = 0; i < 32; i++) {
            const int k = kg * 32 + i;
            const float x = pin[k];
            const float4 w = *(const float4*)(out_w1 + k * ND + j4);
            acc.x = fmaf(x, w.x, acc.x);
            acc.y = fmaf(x, w.y, acc.y);
            acc.z = fmaf(x, w.z, acc.z);
            acc.w = fmaf(x, w.w, acc.w);
        }
        *(float4*)(sPA + kg * ND + j4) = acc;
    }
    __syncthreads();
    if (t < ND) {
        float v = out_b1[t];
#pragma unroll
        for (int g = 0; g < 8; g++) v += sPA[g * ND + t];
        sH[t] = fmaxf(v, 0.f) * out_w2[t];
    }
    __syncthreads();
    if (t < 32) {
        float v = sH[t] + sH[t + 32] + sH[t + 64] + sH[t + 96];
#pragma unroll
        for (int o = 16; o; o >>= 1) v += __shfl_xor_sync(0xffffffffu, v, o);
        if (t == 0) out[b] = 1.f / (1.f + __expf(-(v + out_b2[0])));
    }
}

// ---------------------------------------------------------------------------
extern "C" void kernel_launch(void* const* d_in, const int* in_sizes, int n_in,
                              void* d_out, int out_size) {
    const int*   qseq   = (const int*)  d_in[0];
    // d_in[1] = answer_seq (unused by reference)
    const float* emb    = (const float*)d_in[2];
    const float* keym   = (const float*)d_in[3];
    const float* vu_w1  = (const float*)d_in[4];
    const float* vu_b1  = (const float*)d_in[5];
    const float* vu_w2  = (const float*)d_in[6];
    const float* vu_b2  = (const float*)d_in[7];
    const float* er_w   = (const float*)d_in[8];
    const float* er_b   = (const float*)d_in[9];
    const float* ad_w   = (const float*)d_in[10];
    const float* ad_b   = (const float*)d_in[11];
    const float* out_w1 = (const float*)d_in[12];
    const float* out_b1 = (const float*)d_in[13];
    const float* out_w2 = (const float*)d_in[14];
    const float* out_b2 = (const float*)d_in[15];
    float* out = (float*)d_out;

    cudaFuncSetAttribute(precompute_kernel,
                         cudaFuncAttributeMaxDynamicSharedMemorySize, PRE_SMEM_BYTES);
    cudaFuncSetAttribute(recurrent_kernel,
                         cudaFuncAttributeMaxDynamicSharedMemorySize, SMEM_BYTES);

    precompute_kernel<<<NROW / RPB, 256, PRE_SMEM_BYTES>>>(qseq, emb, keym, vu_w1, vu_b1);
    recurrent_kernel<<<NB, T, SMEM_BYTES>>>(qseq, emb, vu_w1, vu_w2, vu_b2,
                                            er_w, er_b, ad_w, ad_b,
                                            out_w1, out_b1, out_w2, out_b2, out);
}

// round 11
// speedup vs baseline: 1.8611x; 1.0736x over previous
#include <cuda_runtime.h>
#include <cuda_fp16.h>
#include <cstdint>
#include <math.h>

#define NB 128   // batch
#define NS 100   // seq len
#define NM 50    // memory slots
#define ND 128   // dim
#define T  384   // threads: 256 compute + 128 mem
#define AS 52    // padded attn row stride (floats, 16B-aligned rows)

#define NROW (NB * NS)     // 12800 (b,s) rows
#define RPB  32            // rows per precompute block
#define KS   132           // padded key row stride

// Scratch for precomputed attention weights and qe@W1b+b1
__device__ float g_attn[NB * NS * NM];
__device__ float g_q1[NB * NS * ND];

#define BAR256()         asm volatile("bar.sync 1, 256;" ::: "memory")

__device__ __forceinline__ float tanh_fast(float x) {
    float y;
    asm("tanh.approx.f32 %0, %1;" : "=f"(y) : "f"(x));
    return y;
}
__device__ __forceinline__ float sigmoid_fast(float x) {
    return fmaf(0.5f, tanh_fast(0.5f * x), 0.5f);
}

// ---------------------------------------------------------------------------
// K1: tiled batched precompute (unchanged, ~4us)
// ---------------------------------------------------------------------------
#define P_KEY  0
#define P_W1B  (NM * KS)
#define P_QE   (P_W1B + ND * ND)
#define P_B1   (P_QE + RPB * ND)
#define P_IDS  (P_B1 + ND)
#define P_TOTF (P_IDS + RPB)
#define PRE_SMEM_BYTES (P_TOTF * 4)

__global__ __launch_bounds__(256, 1)
void precompute_kernel(const int* __restrict__ qseq,
                       const float* __restrict__ emb,
                       const float* __restrict__ keym,
                       const float* __restrict__ vu_w1,
                       const float* __restrict__ vu_b1) {
    extern __shared__ float ps[];
    float* sKey = ps + P_KEY;
    float* sW1b = ps + P_W1B;
    float* sQe  = ps + P_QE;
    float* sB1  = ps + P_B1;
    int*   sIds = (int*)(ps + P_IDS);

    const int t  = threadIdx.x;
    const int r0 = blockIdx.x * RPB;

    if (t < RPB) sIds[t] = qseq[r0 + t];

    for (int i = t; i < NM * ND / 4; i += 256) {
        const int m = i / 32, c4 = i % 32;
        *(float4*)(sKey + m * KS + c4 * 4) = ((const float4*)keym)[i];
    }
    {
        const float4* src = (const float4*)(vu_w1 + ND * ND);
        for (int i = t; i < ND * ND / 4; i += 256) ((float4*)sW1b)[i] = src[i];
    }
    if (t < ND) sB1[t] = vu_b1[t];
    __syncthreads();

    for (int i = t; i < RPB * 32; i += 256) {
        const int row = i >> 5, c4 = i & 31;
        const float4* src = (const float4*)(emb + (size_t)sIds[row] * ND);
        *(float4*)(sQe + row * ND + c4 * 4) = src[c4];
    }
    __syncthreads();

    {
        const int wid = t >> 5, lid = t & 31;
        const int mB = (lid < NM - 32) ? lid + 32 : lid;
        float acc0[4] = {0, 0, 0, 0}, acc1[4] = {0, 0, 0, 0};
        const float* kA = sKey + lid * KS;
        const float* kB = sKey + mB * KS;
#pragma unroll
        for (int k4 = 0; k4 < 32; k4++) {
            const float4 a = *(const float4*)(kA + k4 * 4);
            const float4 b = *(const float4*)(kB + k4 * 4);
#pragma unroll
            for (int r = 0; r < 4; r++) {
                const float4 q = *(const float4*)(sQe + (wid * 4 + r) * ND + k4 * 4);
                acc0[r] = fmaf(q.x, a.x, fmaf(q.y, a.y, fmaf(q.z, a.z, fmaf(q.w, a.w, acc0[r]))));
                acc1[r] = fmaf(q.x, b.x, fmaf(q.y, b.y, fmaf(q.z, b.z, fmaf(q.w, b.w, acc1[r]))));
            }
        }
        const bool hasB = (lid < NM - 32);
#pragma unroll
        for (int r = 0; r < 4; r++) {
            float v0 = acc0[r];
            float v1 = hasB ? acc1[r] : -1e30f;
            float mx = fmaxf(v0, v1);
#pragma unroll
            for (int o = 16; o; o >>= 1) mx = fmaxf(mx, __shfl_xor_sync(0xffffffffu, mx, o));
            float e0 = __expf(v0 - mx);
            float e1 = hasB ? __expf(v1 - mx) : 0.f;
            float sum = e0 + e1;
#pragma unroll
            for (int o = 16; o; o >>= 1) sum += __shfl_xor_sync(0xffffffffu, sum, o);
            const float inv = 1.f / sum;
            float* dst = g_attn + (size_t)(r0 + wid * 4 + r) * NM;
            dst[lid] = e0 * inv;
            if (hasB) dst[lid + 32] = e1 * inv;
        }
    }

    {
        const int cg = t & 31;
        const int rg = t >> 5;
        float4 acc[4] = {{0,0,0,0},{0,0,0,0},{0,0,0,0},{0,0,0,0}};
#pragma unroll 8
        for (int k4 = 0; k4 < 32; k4++) {
            const float4 w0 = *(const float4*)(sW1b + (k4 * 4 + 0) * ND + cg * 4);
            const float4 w1 = *(const float4*)(sW1b + (k4 * 4 + 1) * ND + cg * 4);
            const float4 w2 = *(const float4*)(sW1b + (k4 * 4 + 2) * ND + cg * 4);
            const float4 w3 = *(const float4*)(sW1b + (k4 * 4 + 3) * ND + cg * 4);
#pragma unroll
            for (int r = 0; r < 4; r++) {
                const float4 q = *(const float4*)(sQe + (rg * 4 + r) * ND + k4 * 4);
                acc[r].x = fmaf(q.x, w0.x, fmaf(q.y, w1.x, fmaf(q.z, w2.x, fmaf(q.w, w3.x, acc[r].x))));
                acc[r].y = fmaf(q.x, w0.y, fmaf(q.y, w1.y, fmaf(q.z, w2.y, fmaf(q.w, w3.y, acc[r].y))));
                acc[r].z = fmaf(q.x, w0.z, fmaf(q.y, w1.z, fmaf(q.z, w2.z, fmaf(q.w, w3.z, acc[r].z))));
                acc[r].w = fmaf(q.x, w0.w, fmaf(q.y, w1.w, fmaf(q.z, w2.w, fmaf(q.w, w3.w, acc[r].w))));
            }
        }
        const float4 b4 = *(const float4*)(sB1 + cg * 4);
#pragma unroll
        for (int r = 0; r < 4; r++) {
            float4 o = acc[r];
            o.x += b4.x; o.y += b4.y; o.z += b4.z; o.w += b4.w;
            *(float4*)(g_q1 + (size_t)(r0 + rg * 4 + r) * ND + cg * 4) = o;
        }
    }
}

// ---------------------------------------------------------------------------
// K2: warp-specialized recurrent kernel; GEMVs in fp16 HFMA2 (half2 acc per
// 16/32-term warp slice, fp32 cross-warp reduce). Identity algebra fp32.
// ---------------------------------------------------------------------------
// smem layout (floats)
#define SM_W1H  0                         // 128*128 half = 8192 floats
#define SM_W2H  8192                      // 8192 floats
#define SM_ATTN 16384                     // 100*52 = 5200 (padded rows)
#define SM_PA   21584                     // 1024 (A partials)
#define SM_PB   22608                     // 1024 (B partials)
#define SM_PC   23632                     // 2 x 1024 (C pre-act partials, parity)
#define SM_READ 25680                     // 128 (tail only)
#define SM_H    25808                     // 128 (tail only)
#define SM_UP   25936                     // 128 (tail only)
#define SM_B2   26064                     // 128
#define SM_BE   26192                     // 128 (er_b)
#define SM_BA   26320                     // 128 (ad_b)
#define SM_R0   26448                     // 2 x 128 (parity)
#define SM_G    26704                     // 2 x 128
#define SM_C    26960                     // 2 (+2 pad)
#define SM_V    26964                     // 50*128 = 6400
#define SM_TOTF (SM_V + NM * ND)
#define SMEM_BYTES (SM_TOTF * 4)

__global__ __launch_bounds__(T, 1)
void recurrent_kernel(const int* __restrict__ qseq,
                      const float* __restrict__ emb,
                      const float* __restrict__ vu_w1,
                      const float* __restrict__ vu_w2,
                      const float* __restrict__ vu_b2,
                      const float* __restrict__ er_w,
                      const float* __restrict__ er_b,
                      const float* __restrict__ ad_w,
                      const float* __restrict__ ad_b,
                      const float* __restrict__ out_w1,
                      const float* __restrict__ out_b1,
                      const float* __restrict__ out_w2,
                      const float* __restrict__ out_b2,
                      float* __restrict__ out) {
    extern __shared__ float sm[];
    __half* sW1h = (__half*)(sm + SM_W1H);
    __half* sW2h = (__half*)(sm + SM_W2H);
    float* sAttn = sm + SM_ATTN;
    float* sPA   = sm + SM_PA;
    float* sPB   = sm + SM_PB;
    float* sPC   = sm + SM_PC;
    float* sRead = sm + SM_READ;
    float* sH    = sm + SM_H;
    float* sUp   = sm + SM_UP;
    float* sV    = sm + SM_V;

    const int b = blockIdx.x;
    const int t = threadIdx.x;

    // ---- shared init ----
    for (int i = t; i < ND * ND; i += T) {
        sW1h[i] = __float2half_rn(vu_w1[i]);
        sW2h[i] = __float2half_rn(vu_w2[i]);
    }
    for (int i = t; i < NS * NM; i += T)
        sAttn[(i / NM) * AS + (i % NM)] = g_attn[b * NS * NM + i];
    for (int i = t; i < 2 * 1024; i += T) sPC[i] = 0.f;
    for (int i = t; i < 2 * ND * 2 + 4; i += T) sm[SM_R0 + i] = 0.f;  // r0/g/c
    for (int i = t; i < NM * ND; i += T) sV[i] = 0.f;
    if (t < ND) {
        sm[SM_B2 + t] = vu_b2[t];
        sm[SM_BE + t] = er_b[t];
        sm[SM_BA + t] = ad_b[t];
    }

    // ---- compute-role register state: er/ad weights as packed half2 ----
    const int lid = t & 31;
    const int jq = t & 63;
    const int ks = (t >> 6) & 3;
    __half2 eah01[32], eah23[32];
    if (t < 256) {
        const float* src = (jq < 32) ? (er_w + jq * 4) : (ad_w + (jq - 32) * 4);
#pragma unroll
        for (int kk = 0; kk < 32; kk++) {
            const float4 w4 = *(const float4*)(src + (ks * 32 + kk) * ND);
            eah01[kk] = __floats2half2_rn(w4.x, w4.y);
            eah23[kk] = __floats2half2_rn(w4.z, w4.w);
        }
    }
    const int u = t - 256;         // 0..127 for mem threads (one d-column each)

    // compute stage mappings
    const int j4 = (t & 31) * 4;
    const int kg = (t >> 5) & 7;       // warp id for compute warps
    const int kownA = kg * 16 + (lid & 15);   // A/B prologue slice (16 k per warp)
    const int kownC = ks * 32 + lid;          // C prologue slice

    __syncthreads();

    const float* q1b = g_q1 + b * NS * ND;

    for (int s = 0; s < NS; s++) {
        const int par  = s & 1;         // sPC written this step; r0/g/c consumed
        const int parm = (s + 1) & 1;   // sPC from previous step; r0/g/c written

        if (t < 256) {
            // prefetch q1 for this warp's k-slice (consumed in B prologue)
            const float q1f = q1b[s * ND + kownA];
            const float* pc = sPC + parm * 1024;

            // ---- A prologue: reconstruct e/a at kownA, then read value ----
            float rd;
            {
                float pe = sm[SM_BE + kownA];
                float pa = sm[SM_BA + kownA];
#pragma unroll
                for (int g = 0; g < 4; g++) {
                    pe += pc[g * 256 + kownA];
                    pa += pc[g * 256 + 128 + kownA];
                }
                const float e = sigmoid_fast(pe);
                const float a = tanh_fast(pa);
                const float r0 = sm[SM_R0 + par * ND + kownA];
                const float gg = sm[SM_G  + par * ND + kownA];
                const float cc = sm[SM_C  + par];
                rd = fmaf(cc, a, fmaf(-e, gg, r0));
            }
            // ---- A GEMV (fp16): x as dup'd half2 broadcast via shfl ----
            {
                const __half2 rh2 = __float2half2_rn(rd);
                const unsigned ru = *(const unsigned*)&rh2;
                __half2 acc01 = __floats2half2_rn(0.f, 0.f);
                __half2 acc23 = acc01;
                const __half* wrow = sW1h + (kg * 16) * ND + j4;
#pragma unroll
                for (int i = 0; i < 16; i++) {
                    const unsigned xs = __shfl_sync(0xffffffffu, ru, i);
                    const __half2 xh = *(const __half2*)&xs;
                    const uint2 raw = *(const uint2*)(wrow + i * ND);
                    acc01 = __hfma2(xh, *(const __half2*)&raw.x, acc01);
                    acc23 = __hfma2(xh, *(const __half2*)&raw.y, acc23);
                }
                const float2 f01 = __half22float2(acc01);
                const float2 f23 = __half22float2(acc23);
                float4 o = {f01.x, f01.y, f23.x, f23.y};
                *(float4*)(sPA + kg * ND + j4) = o;
            }
            BAR256();

            // ---- B prologue: h[kownA] = tanh(q1 + sum partials) ----
            float hv;
            {
                float v = q1f;
#pragma unroll
                for (int g = 0; g < 8; g++) v += sPA[g * ND + kownA];
                hv = tanh_fast(v);
            }
            // ---- B GEMV (fp16) ----
            {
                const __half2 hh2 = __float2half2_rn(hv);
                const unsigned hu = *(const unsigned*)&hh2;
                __half2 acc01 = __floats2half2_rn(0.f, 0.f);
                __half2 acc23 = acc01;
                const __half* wrow = sW2h + (kg * 16) * ND + j4;
#pragma unroll
                for (int i = 0; i < 16; i++) {
                    const unsigned xs = __shfl_sync(0xffffffffu, hu, i);
                    const __half2 xh = *(const __half2*)&xs;
                    const uint2 raw = *(const uint2*)(wrow + i * ND);
                    acc01 = __hfma2(xh, *(const __half2*)&raw.x, acc01);
                    acc23 = __hfma2(xh, *(const __half2*)&raw.y, acc23);
                }
                const float2 f01 = __half22float2(acc01);
                const float2 f23 = __half22float2(acc23);
                float4 o = {f01.x, f01.y, f23.x, f23.y};
                *(float4*)(sPB + kg * ND + j4) = o;
            }
            BAR256();

            // ---- C prologue: up[kownC] = b2 + sum partials ----
            float upv;
            {
                float v = sm[SM_B2 + kownC];
#pragma unroll
                for (int g = 0; g < 8; g++) v += sPB[g * ND + kownC];
                upv = v;
            }
            // ---- C GEMV (fp16): e/a pre-activation partials ----
            {
                const __half2 uh2 = __float2half2_rn(upv);
                const unsigned uu = *(const unsigned*)&uh2;
                __half2 acc01 = __floats2half2_rn(0.f, 0.f);
                __half2 acc23 = acc01;
#pragma unroll
                for (int i = 0; i < 32; i++) {
                    const unsigned xs = __shfl_sync(0xffffffffu, uu, i);
                    const __half2 xh = *(const __half2*)&xs;
                    acc01 = __hfma2(xh, eah01[i], acc01);
                    acc23 = __hfma2(xh, eah23[i], acc23);
                }
                const float2 p01 = __half22float2(acc01);
                const float2 p23 = __half22float2(acc23);
                float4 o = {p01.x, p01.y, p23.x, p23.y};
                *(float4*)(sPC + par * 1024 + ks * 256 + jq * 4) = o;
            }
        } else {
            // ---- mem warps: reconstruct e/a at u, update sV, r0/g/c for s+1 ----
            const float* wu  = sAttn + (s ? (s - 1) * AS : 0);
            const float* wsr = sAttn + s * AS;
            const float* wr  = sAttn + ((s + 1 < NS) ? (s + 1) : (NS - 1)) * AS;
            float e, a;
            if (s == 0) {
                e = 0.f; a = 0.f;   // v=0: step-0 "update" must be a no-op
            } else {
                const float* pc = sPC + parm * 1024;
                float pe = sm[SM_BE + u];
                float pa = sm[SM_BA + u];
#pragma unroll
                for (int g = 0; g < 4; g++) {
                    pe += pc[g * 256 + u];
                    pa += pc[g * 256 + 128 + u];
                }
                e = sigmoid_fast(pe);
                a = tanh_fast(pa);
            }
            const float ne = -e;
            float r0v = 0.f, gv = 0.f, cacc = 0.f;

#define MEMSTEP(wum, wsm, wrm, m) { \
    float v = sV[(m) * ND + u]; \
    v = fmaf(wum, fmaf(ne, v, a), v); \
    sV[(m) * ND + u] = v; \
    const float p = (wrm) * v; \
    r0v += p; \
    gv   = fmaf(wsm, p, gv); \
    cacc = fmaf(wrm, wsm, cacc); }

#pragma unroll
            for (int mq = 0; mq < 12; mq++) {
                const float4 wu4 = *(const float4*)(wu  + mq * 4);
                const float4 ws4 = *(const float4*)(wsr + mq * 4);
                const float4 wr4 = *(const float4*)(wr  + mq * 4);
                MEMSTEP(wu4.x, ws4.x, wr4.x, mq * 4 + 0)
                MEMSTEP(wu4.y, ws4.y, wr4.y, mq * 4 + 1)
                MEMSTEP(wu4.z, ws4.z, wr4.z, mq * 4 + 2)
                MEMSTEP(wu4.w, ws4.w, wr4.w, mq * 4 + 3)
            }
            {
                const float2 wu2 = *(const float2*)(wu  + 48);
                const float2 ws2 = *(const float2*)(wsr + 48);
                const float2 wr2 = *(const float2*)(wr  + 48);
                MEMSTEP(wu2.x, ws2.x, wr2.x, 48)
                MEMSTEP(wu2.y, ws2.y, wr2.y, 49)
            }
#undef MEMSTEP
            sm[SM_R0 + parm * ND + u] = r0v;
            sm[SM_G  + parm * ND + u] = gv;
            if (u == 0) sm[SM_C + parm] = cacc;
        }
        __syncthreads();
    }

    // ---- tail: read_out = w_99 . v_100 via the same identity ----
    if (t < ND) {
        const float* pc = sPC + 1024;       // parity of s=99
        float pe = sm[SM_BE + t];
        float pa = sm[SM_BA + t];
#pragma unroll
        for (int g = 0; g < 4; g++) {
            pe += pc[g * 256 + t];
            pa += pc[g * 256 + 128 + t];
        }
        const float e = sigmoid_fast(pe);
        const float a = tanh_fast(pa);
        const float r0 = sm[SM_R0 + t];     // parity 0 (written at s=99)
        const float gg = sm[SM_G  + t];
        const float cc = sm[SM_C];
        sRead[t] = fmaf(cc, a, fmaf(-e, gg, r0));
        const int qi = qseq[b * NS + (NS - 1)];
        sUp[t] = emb[qi * ND + t];   // qe_last
    }
    __syncthreads();

    // ---- output head (fp32 weights from global; one-shot) ----
    if (t < 256) {
        const float* pin = (kg < 4) ? sRead : (sUp - ND);
        float4 acc = {0.f, 0.f, 0.f, 0.f};
#pragma unroll
        for (int i = 0; i < 32; i++) {
            const int k = kg * 32 + i;
            const float x = pin[k];
            const float4 w = *(const float4*)(out_w1 + k * ND + j4);
            acc.x = fmaf(x, w.x, acc.x);
            acc.y = fmaf(x, w.y, acc.y);
            acc.z = fmaf(x, w.z, acc.z);
            acc.w = fmaf(x, w.w, acc.w);
        }
        *(float4*)(sPA + kg * ND + j4) = acc;
    }
    __syncthreads();
    if (t < ND) {
        float v = out_b1[t];
#pragma unroll
        for (int g = 0; g < 8; g++) v += sPA[g * ND + t];
        sH[t] = fmaxf(v, 0.f) * out_w2[t];
    }
    __syncthreads();
    if (t < 32) {
        float v = sH[t] + sH[t + 32] + sH[t + 64] + sH[t + 96];
#pragma unroll
        for (int o = 16; o; o >>= 1) v += __shfl_xor_sync(0xffffffffu, v, o);
        if (t == 0) out[b] = 1.f / (1.f + __expf(-(v + out_b2[0])));
    }
}

// ---------------------------------------------------------------------------
extern "C" void kernel_launch(void* const* d_in, const int* in_sizes, int n_in,
                              void* d_out, int out_size) {
    const int*   qseq   = (const int*)  d_in[0];
    // d_in[1] = answer_seq (unused by reference)
    const float* emb    = (const float*)d_in[2];
    const float* keym   = (const float*)d_in[3];
    const float* vu_w1  = (const float*)d_in[4];
    const float* vu_b1  = (const float*)d_in[5];
    const float* vu_w2  = (const float*)d_in[6];
    const float* vu_b2  = (const float*)d_in[7];
    const float* er_w   = (const float*)d_in[8];
    const float* er_b   = (const float*)d_in[9];
    const float* ad_w   = (const float*)d_in[10];
    const float* ad_b   = (const float*)d_in[11];
    const float* out_w1 = (const float*)d_in[12];
    const float* out_b1 = (const float*)d_in[13];
    const float* out_w2 = (const float*)d_in[14];
    const float* out_b2 = (const float*)d_in[15];
    float* out = (float*)d_out;

    cudaFuncSetAttribute(precompute_kernel,
                         cudaFuncAttributeMaxDynamicSharedMemorySize, PRE_SMEM_BYTES);
    cudaFuncSetAttribute(recurrent_kernel,
                         cudaFuncAttributeMaxDynamicSharedMemorySize, SMEM_BYTES);

    precompute_kernel<<<NROW / RPB, 256, PRE_SMEM_BYTES>>>(qseq, emb, keym, vu_w1, vu_b1);
    recurrent_kernel<<<NB, T, SMEM_BYTES>>>(qseq, emb, vu_w1, vu_w2, vu_b2,
                                            er_w, er_b, ad_w, ad_b,
                                            out_w1, out_b1, out_w2, out_b2, out);
}

// round 12
// speedup vs baseline: 2.1910x; 1.1773x over previous
#include <cuda_runtime.h>
#include <cuda_fp16.h>
#include <cstdint>
#include <math.h>

#define NB 128   // batch
#define NS 100   // seq len
#define NM 50    // memory slots
#define ND 128   // dim
#define T  384   // threads: 256 compute + 128 mem
#define AS 52    // padded attn row stride (floats, 16B-aligned rows)

#define NROW (NB * NS)     // 12800 (b,s) rows
#define RPB  32            // rows per precompute block
#define KS   132           // padded key row stride

// Scratch: attention weights, qe@W1b+b1, fused matrix M = W2@[er|ad], bias
__device__ float g_attn[NB * NS * NM];
__device__ float g_q1[NB * NS * ND];
__device__ __half g_M[ND * 2 * ND];     // [k][j], j in 0..255 (e then a)
__device__ float  g_bias[2 * ND];       // b2@[er|ad] + [er_b|ad_b]

#define BAR256()         asm volatile("bar.sync 1, 256;" ::: "memory")

__device__ __forceinline__ float tanh_fast(float x) {
    float y;
    asm("tanh.approx.f32 %0, %1;" : "=f"(y) : "f"(x));
    return y;
}
__device__ __forceinline__ float sigmoid_fast(float x) {
    return fmaf(0.5f, tanh_fast(0.5f * x), 0.5f);
}

// ---------------------------------------------------------------------------
// K0: combine W2 with er/ad:  M[k][j] = sum_i W2[k][i]*E[i][j],
//     bias[j] = sum_i b2[i]*E[i][j] + eb[j].   grid=128 (k), block=256 (j).
// ---------------------------------------------------------------------------
__global__ __launch_bounds__(256, 1)
void combine_kernel(const float* __restrict__ vu_w2,
                    const float* __restrict__ vu_b2,
                    const float* __restrict__ er_w,
                    const float* __restrict__ er_b,
                    const float* __restrict__ ad_w,
                    const float* __restrict__ ad_b) {
    __shared__ float w2row[ND];
    const int k = blockIdx.x;
    const int j = threadIdx.x;
    for (int i = j; i < ND; i += 256) w2row[i] = vu_w2[k * ND + i];
    __syncthreads();
    const float* E = (j < ND) ? er_w : ad_w;
    const int jj = j & (ND - 1);
    float acc = 0.f;
#pragma unroll 8
    for (int i = 0; i < ND; i++) acc = fmaf(w2row[i], E[i * ND + jj], acc);
    g_M[k * 2 * ND + j] = __float2half_rn(acc);
    if (k == 0) {
        float bacc = (j < ND) ? er_b[jj] : ad_b[jj];
        for (int i = 0; i < ND; i++) bacc = fmaf(vu_b2[i], E[i * ND + jj], bacc);
        g_bias[j] = bacc;
    }
}

// ---------------------------------------------------------------------------
// K1: tiled batched precompute (unchanged, ~4us)
// ---------------------------------------------------------------------------
#define P_KEY  0
#define P_W1B  (NM * KS)
#define P_QE   (P_W1B + ND * ND)
#define P_B1   (P_QE + RPB * ND)
#define P_IDS  (P_B1 + ND)
#define P_TOTF (P_IDS + RPB)
#define PRE_SMEM_BYTES (P_TOTF * 4)

__global__ __launch_bounds__(256, 1)
void precompute_kernel(const int* __restrict__ qseq,
                       const float* __restrict__ emb,
                       const float* __restrict__ keym,
                       const float* __restrict__ vu_w1,
                       const float* __restrict__ vu_b1) {
    extern __shared__ float ps[];
    float* sKey = ps + P_KEY;
    float* sW1b = ps + P_W1B;
    float* sQe  = ps + P_QE;
    float* sB1  = ps + P_B1;
    int*   sIds = (int*)(ps + P_IDS);

    const int t  = threadIdx.x;
    const int r0 = blockIdx.x * RPB;

    if (t < RPB) sIds[t] = qseq[r0 + t];

    for (int i = t; i < NM * ND / 4; i += 256) {
        const int m = i / 32, c4 = i % 32;
        *(float4*)(sKey + m * KS + c4 * 4) = ((const float4*)keym)[i];
    }
    {
        const float4* src = (const float4*)(vu_w1 + ND * ND);
        for (int i = t; i < ND * ND / 4; i += 256) ((float4*)sW1b)[i] = src[i];
    }
    if (t < ND) sB1[t] = vu_b1[t];
    __syncthreads();

    for (int i = t; i < RPB * 32; i += 256) {
        const int row = i >> 5, c4 = i & 31;
        const float4* src = (const float4*)(emb + (size_t)sIds[row] * ND);
        *(float4*)(sQe + row * ND + c4 * 4) = src[c4];
    }
    __syncthreads();

    {
        const int wid = t >> 5, lid = t & 31;
        const int mB = (lid < NM - 32) ? lid + 32 : lid;
        float acc0[4] = {0, 0, 0, 0}, acc1[4] = {0, 0, 0, 0};
        const float* kA = sKey + lid * KS;
        const float* kB = sKey + mB * KS;
#pragma unroll
        for (int k4 = 0; k4 < 32; k4++) {
            const float4 a = *(const float4*)(kA + k4 * 4);
            const float4 b = *(const float4*)(kB + k4 * 4);
#pragma unroll
            for (int r = 0; r < 4; r++) {
                const float4 q = *(const float4*)(sQe + (wid * 4 + r) * ND + k4 * 4);
                acc0[r] = fmaf(q.x, a.x, fmaf(q.y, a.y, fmaf(q.z, a.z, fmaf(q.w, a.w, acc0[r]))));
                acc1[r] = fmaf(q.x, b.x, fmaf(q.y, b.y, fmaf(q.z, b.z, fmaf(q.w, b.w, acc1[r]))));
            }
        }
        const bool hasB = (lid < NM - 32);
#pragma unroll
        for (int r = 0; r < 4; r++) {
            float v0 = acc0[r];
            float v1 = hasB ? acc1[r] : -1e30f;
            float mx = fmaxf(v0, v1);
#pragma unroll
            for (int o = 16; o; o >>= 1) mx = fmaxf(mx, __shfl_xor_sync(0xffffffffu, mx, o));
            float e0 = __expf(v0 - mx);
            float e1 = hasB ? __expf(v1 - mx) : 0.f;
            float sum = e0 + e1;
#pragma unroll
            for (int o = 16; o; o >>= 1) sum += __shfl_xor_sync(0xffffffffu, sum, o);
            const float inv = 1.f / sum;
            float* dst = g_attn + (size_t)(r0 + wid * 4 + r) * NM;
            dst[lid] = e0 * inv;
            if (hasB) dst[lid + 32] = e1 * inv;
        }
    }

    {
        const int cg = t & 31;
        const int rg = t >> 5;
        float4 acc[4] = {{0,0,0,0},{0,0,0,0},{0,0,0,0},{0,0,0,0}};
#pragma unroll 8
        for (int k4 = 0; k4 < 32; k4++) {
            const float4 w0 = *(const float4*)(sW1b + (k4 * 4 + 0) * ND + cg * 4);
            const float4 w1 = *(const float4*)(sW1b + (k4 * 4 + 1) * ND + cg * 4);
            const float4 w2 = *(const float4*)(sW1b + (k4 * 4 + 2) * ND + cg * 4);
            const float4 w3 = *(const float4*)(sW1b + (k4 * 4 + 3) * ND + cg * 4);
#pragma unroll
            for (int r = 0; r < 4; r++) {
                const float4 q = *(const float4*)(sQe + (rg * 4 + r) * ND + k4 * 4);
                acc[r].x = fmaf(q.x, w0.x, fmaf(q.y, w1.x, fmaf(q.z, w2.x, fmaf(q.w, w3.x, acc[r].x))));
                acc[r].y = fmaf(q.x, w0.y, fmaf(q.y, w1.y, fmaf(q.z, w2.y, fmaf(q.w, w3.y, acc[r].y))));
                acc[r].z = fmaf(q.x, w0.z, fmaf(q.y, w1.z, fmaf(q.z, w2.z, fmaf(q.w, w3.z, acc[r].z))));
                acc[r].w = fmaf(q.x, w0.w, fmaf(q.y, w1.w, fmaf(q.z, w2.w, fmaf(q.w, w3.w, acc[r].w))));
            }
        }
        const float4 b4 = *(const float4*)(sB1 + cg * 4);
#pragma unroll
        for (int r = 0; r < 4; r++) {
            float4 o = acc[r];
            o.x += b4.x; o.y += b4.y; o.z += b4.z; o.w += b4.w;
            *(float4*)(g_q1 + (size_t)(r0 + rg * 4 + r) * ND + cg * 4) = o;
        }
    }
}

// ---------------------------------------------------------------------------
// K2: warp-specialized recurrent kernel, B stage fused away.
// Per step: A-pro(+act) A-GEMV BAR M-pro M-GEMV || mem  syncthreads.
// M (=W2@[er|ad]) held in registers (64 half2/compute thread).
// Mem warps: float2 over 2 d-columns x half m-range; r0/g/c are 2-partial.
// ---------------------------------------------------------------------------
// smem layout (floats)
#define SM_W1H  0                         // 128*128 half = 8192 floats
#define SM_ATTN 8192                      // 100*52 = 5200 (padded rows)
#define SM_PA   13392                     // 1024 (A partials)
#define SM_PC   14416                     // 2 x 1024 (pre-act partials, parity)
#define SM_READ 16464                     // 128 (tail only)
#define SM_H    16592                     // 128 (tail only)
#define SM_UP   16720                     // 128 (tail only)
#define SM_BE   16848                     // 128 (bias_e)
#define SM_BA   16976                     // 128 (bias_a)
#define SM_R0   17104                     // 2 x 256 (parity x 2 halves)
#define SM_G    17616                     // 2 x 256
#define SM_C    18128                     // 2 x 2 (+4 pad)
#define SM_V    18136                     // 50*128 = 6400
#define SM_TOTF (SM_V + NM * ND)
#define SMEM_BYTES (SM_TOTF * 4)

__global__ __launch_bounds__(T, 1)
void recurrent_kernel(const int* __restrict__ qseq,
                      const float* __restrict__ emb,
                      const float* __restrict__ vu_w1,
                      const float* __restrict__ out_w1,
                      const float* __restrict__ out_b1,
                      const float* __restrict__ out_w2,
                      const float* __restrict__ out_b2,
                      float* __restrict__ out) {
    extern __shared__ float sm[];
    __half* sW1h = (__half*)(sm + SM_W1H);
    float* sAttn = sm + SM_ATTN;
    float* sPA   = sm + SM_PA;
    float* sPC   = sm + SM_PC;
    float* sRead = sm + SM_READ;
    float* sH    = sm + SM_H;
    float* sUp   = sm + SM_UP;
    float* sV    = sm + SM_V;

    const int b = blockIdx.x;
    const int t = threadIdx.x;

    // ---- shared init ----
    for (int i = t; i < ND * ND; i += T) sW1h[i] = __float2half_rn(vu_w1[i]);
    for (int i = t; i < NS * NM; i += T)
        sAttn[(i / NM) * AS + (i % NM)] = g_attn[b * NS * NM + i];
    for (int i = t; i < 2 * 1024; i += T) sPC[i] = 0.f;
    for (int i = t; i < 1032; i += T) sm[SM_R0 + i] = 0.f;   // r0/g/c region
    for (int i = t; i < NM * ND; i += T) sV[i] = 0.f;
    if (t < ND) {
        sm[SM_BE + t] = g_bias[t];
        sm[SM_BA + t] = g_bias[ND + t];
    }

    // ---- compute-role registers: fused matrix M as packed half2 ----
    const int lid = t & 31;
    const int jq = t & 63;            // output quad (256 outputs / 4)
    const int ks = (t >> 6) & 3;      // k-slice of 32
    __half2 mh01[32], mh23[32];
    if (t < 256) {
#pragma unroll
        for (int kk = 0; kk < 32; kk++) {
            const uint2 raw = *(const uint2*)(g_M + (ks * 32 + kk) * 2 * ND + jq * 4);
            mh01[kk] = *(const __half2*)&raw.x;
            mh23[kk] = *(const __half2*)&raw.y;
        }
    }
    // mem-role mapping: 2 d-columns, half m-range
    const int u2 = t - 256;           // 0..127
    const int hh = u2 >> 6;           // m-half: 0 -> m 0..23, 1 -> m 24..49
    const int c2 = (u2 & 63) * 2;     // d-column pair

    // compute stage mappings
    const int j4 = (t & 31) * 4;
    const int kg = (t >> 5) & 7;              // compute warp id
    const int kownA = kg * 16 + (lid & 15);   // A slice (16 k per warp)
    const int kownC = ks * 32 + lid;          // M slice (32 k per warp)

    __syncthreads();

    const float* q1b = g_q1 + b * NS * ND;

    for (int s = 0; s < NS; s++) {
        const int par  = s & 1;         // sPC written; r0/g/c consumed
        const int parm = (s + 1) & 1;   // sPC from prev step; r0/g/c written

        if (t < 256) {
            const float q1f = q1b[s * ND + kownC];
            const float* pc = sPC + parm * 1024;

            // ---- A prologue: reconstruct e/a at kownA, then read value ----
            float rd;
            {
                float pe = sm[SM_BE + kownA];
                float pa = sm[SM_BA + kownA];
#pragma unroll
                for (int g = 0; g < 4; g++) {
                    pe += pc[g * 256 + kownA];
                    pa += pc[g * 256 + 128 + kownA];
                }
                const float e = sigmoid_fast(pe);
                const float a = tanh_fast(pa);
                const float r0 = sm[SM_R0 + par * 256 + kownA]
                               + sm[SM_R0 + par * 256 + 128 + kownA];
                const float gg = sm[SM_G + par * 256 + kownA]
                               + sm[SM_G + par * 256 + 128 + kownA];
                const float cc = sm[SM_C + par * 2] + sm[SM_C + par * 2 + 1];
                rd = fmaf(cc, a, fmaf(-e, gg, r0));
            }
            // ---- A GEMV (fp16): x as dup'd half2 broadcast via shfl ----
            {
                const __half2 rh2 = __float2half2_rn(rd);
                const unsigned ru = *(const unsigned*)&rh2;
                __half2 acc01 = __floats2half2_rn(0.f, 0.f);
                __half2 acc23 = acc01;
                const __half* wrow = sW1h + (kg * 16) * ND + j4;
#pragma unroll
                for (int i = 0; i < 16; i++) {
                    const unsigned xs = __shfl_sync(0xffffffffu, ru, i);
                    const __half2 xh = *(const __half2*)&xs;
                    const uint2 raw = *(const uint2*)(wrow + i * ND);
                    acc01 = __hfma2(xh, *(const __half2*)&raw.x, acc01);
                    acc23 = __hfma2(xh, *(const __half2*)&raw.y, acc23);
                }
                const float2 f01 = __half22float2(acc01);
                const float2 f23 = __half22float2(acc23);
                float4 o = {f01.x, f01.y, f23.x, f23.y};
                *(float4*)(sPA + kg * ND + j4) = o;
            }
            BAR256();

            // ---- M prologue: h[kownC] = tanh(q1 + sum partials) ----
            float hv;
            {
                float v = q1f;
#pragma unroll
                for (int g = 0; g < 8; g++) v += sPA[g * ND + kownC];
                hv = tanh_fast(v);
            }
            // ---- M GEMV (fp16): 256 pre-act outputs ----
            {
                const __half2 hh2 = __float2half2_rn(hv);
                const unsigned hu = *(const unsigned*)&hh2;
                __half2 acc01 = __floats2half2_rn(0.f, 0.f);
                __half2 acc23 = acc01;
#pragma unroll
                for (int i = 0; i < 32; i++) {
                    const unsigned xs = __shfl_sync(0xffffffffu, hu, i);
                    const __half2 xh = *(const __half2*)&xs;
                    acc01 = __hfma2(xh, mh01[i], acc01);
                    acc23 = __hfma2(xh, mh23[i], acc23);
                }
                const float2 p01 = __half22float2(acc01);
                const float2 p23 = __half22float2(acc23);
                float4 o = {p01.x, p01.y, p23.x, p23.y};
                *(float4*)(sPC + par * 1024 + ks * 256 + jq * 4) = o;
            }
        } else {
            // ---- mem warps: 2 columns x half m-range ----
            const int moff = hh ? 24 : 0;
            const float* wub = sAttn + (s ? (s - 1) * AS : 0) + moff;
            const float* wsb = sAttn + s * AS + moff;
            const float* wrb = sAttn + ((s + 1 < NS) ? (s + 1) : (NS - 1)) * AS + moff;
            float2 ev, av;
            if (s == 0) {
                ev.x = ev.y = av.x = av.y = 0.f;
            } else {
                const float* pc = sPC + parm * 1024;
                float2 pe = *(const float2*)(sm + SM_BE + c2);
                float2 pa = *(const float2*)(sm + SM_BA + c2);
#pragma unroll
                for (int g = 0; g < 4; g++) {
                    const float2 q = *(const float2*)(pc + g * 256 + c2);
                    const float2 r = *(const float2*)(pc + g * 256 + 128 + c2);
                    pe.x += q.x; pe.y += q.y;
                    pa.x += r.x; pa.y += r.y;
                }
                ev.x = sigmoid_fast(pe.x); ev.y = sigmoid_fast(pe.y);
                av.x = tanh_fast(pa.x);    av.y = tanh_fast(pa.y);
            }
            const float nex = -ev.x, ney = -ev.y;
            float2 r0v = {0.f, 0.f}, gv = {0.f, 0.f};
            float cacc = 0.f;

#define MEM2(wum, wsm, wrm, m) { \
    float2 v = *(float2*)(sV + (m) * ND + c2); \
    v.x = fmaf(wum, fmaf(nex, v.x, av.x), v.x); \
    v.y = fmaf(wum, fmaf(ney, v.y, av.y), v.y); \
    *(float2*)(sV + (m) * ND + c2) = v; \
    const float px = (wrm) * v.x, py = (wrm) * v.y; \
    r0v.x += px; r0v.y += py; \
    gv.x = fmaf(wsm, px, gv.x); gv.y = fmaf(wsm, py, gv.y); \
    cacc = fmaf(wrm, wsm, cacc); }

#pragma unroll
            for (int q = 0; q < 6; q++) {
                const float4 wu4 = *(const float4*)(wub + q * 4);
                const float4 ws4 = *(const float4*)(wsb + q * 4);
                const float4 wr4 = *(const float4*)(wrb + q * 4);
                MEM2(wu4.x, ws4.x, wr4.x, moff + q * 4 + 0)
                MEM2(wu4.y, ws4.y, wr4.y, moff + q * 4 + 1)
                MEM2(wu4.z, ws4.z, wr4.z, moff + q * 4 + 2)
                MEM2(wu4.w, ws4.w, wr4.w, moff + q * 4 + 3)
            }
            if (hh) {
                const float2 wu2 = *(const float2*)(wub + 24);
                const float2 ws2 = *(const float2*)(wsb + 24);
                const float2 wr2 = *(const float2*)(wrb + 24);
                MEM2(wu2.x, ws2.x, wr2.x, 48)
                MEM2(wu2.y, ws2.y, wr2.y, 49)
            }
#undef MEM2
            *(float2*)(sm + SM_R0 + parm * 256 + hh * 128 + c2) = r0v;
            *(float2*)(sm + SM_G  + parm * 256 + hh * 128 + c2) = gv;
            if ((u2 & 63) == 0) sm[SM_C + parm * 2 + hh] = cacc;
        }
        __syncthreads();
    }

    // ---- tail: read_out = w_99 . v_100 via the same identity ----
    if (t < ND) {
        const float* pc = sPC + 1024;       // parity of s=99
        float pe = sm[SM_BE + t];
        float pa = sm[SM_BA + t];
#pragma unroll
        for (int g = 0; g < 4; g++) {
            pe += pc[g * 256 + t];
            pa += pc[g * 256 + 128 + t];
        }
        const float e = sigmoid_fast(pe);
        const float a = tanh_fast(pa);
        const float r0 = sm[SM_R0 + t] + sm[SM_R0 + 128 + t];   // parity 0
        const float gg = sm[SM_G + t] + sm[SM_G + 128 + t];
        const float cc = sm[SM_C] + sm[SM_C + 1];
        sRead[t] = fmaf(cc, a, fmaf(-e, gg, r0));
        const int qi = qseq[b * NS + (NS - 1)];
        sUp[t] = emb[qi * ND + t];   // qe_last
    }
    __syncthreads();

    // ---- output head (fp32 weights from global; one-shot) ----
    if (t < 256) {
        const float* pin = (kg < 4) ? sRead : (sUp - ND);
        float4 acc = {0.f, 0.f, 0.f, 0.f};
#pragma unroll
        for (int i = 0; i < 32; i++) {
            const int k = kg * 32 + i;
            const float x = pin[k];
            const float4 w = *(const float4*)(out_w1 + k * ND + j4);
            acc.x = fmaf(x, w.x, acc.x);
            acc.y = fmaf(x, w.y, acc.y);
            acc.z = fmaf(x, w.z, acc.z);
            acc.w = fmaf(x, w.w, acc.w);
        }
        *(float4*)(sPA + kg * ND + j4) = acc;
    }
    __syncthreads();
    if (t < ND) {
        float v = out_b1[t];
#pragma unroll
        for (int g = 0; g < 8; g++) v += sPA[g * ND + t];
        sH[t] = fmaxf(v, 0.f) * out_w2[t];
    }
    __syncthreads();
    if (t < 32) {
        float v = sH[t] + sH[t + 32] + sH[t + 64] + sH[t + 96];
#pragma unroll
        for (int o = 16; o; o >>= 1) v += __shfl_xor_sync(0xffffffffu, v, o);
        if (t == 0) out[b] = 1.f / (1.f + __expf(-(v + out_b2[0])));
    }
}

// ---------------------------------------------------------------------------
extern "C" void kernel_launch(void* const* d_in, const int* in_sizes, int n_in,
                              void* d_out, int out_size) {
    const int*   qseq   = (const int*)  d_in[0];
    // d_in[1] = answer_seq (unused by reference)
    const float* emb    = (const float*)d_in[2];
    const float* keym   = (const float*)d_in[3];
    const float* vu_w1  = (const float*)d_in[4];
    const float* vu_b1  = (const float*)d_in[5];
    const float* vu_w2  = (const float*)d_in[6];
    const float* vu_b2  = (const float*)d_in[7];
    const float* er_w   = (const float*)d_in[8];
    const float* er_b   = (const float*)d_in[9];
    const float* ad_w   = (const float*)d_in[10];
    const float* ad_b   = (const float*)d_in[11];
    const float* out_w1 = (const float*)d_in[12];
    const float* out_b1 = (const float*)d_in[13];
    const float* out_w2 = (const float*)d_in[14];
    const float* out_b2 = (const float*)d_in[15];
    float* out = (float*)d_out;

    cudaFuncSetAttribute(precompute_kernel,
                         cudaFuncAttributeMaxDynamicSharedMemorySize, PRE_SMEM_BYTES);
    cudaFuncSetAttribute(recurrent_kernel,
                         cudaFuncAttributeMaxDynamicSharedMemorySize, SMEM_BYTES);

    precompute_kernel<<<NROW / RPB, 256, PRE_SMEM_BYTES>>>(qseq, emb, keym, vu_w1, vu_b1);
    combine_kernel<<<ND, 256>>>(vu_w2, vu_b2, er_w, er_b, ad_w, ad_b);
    recurrent_kernel<<<NB, T, SMEM_BYTES>>>(qseq, emb, vu_w1,
                                            out_w1, out_b1, out_w2, out_b2, out);
}

// round 13
// speedup vs baseline: 2.3162x; 1.0571x over previous
#include <cuda_runtime.h>
#include <cuda_fp16.h>
#include <cstdint>
#include <math.h>

#define NB 128   // batch
#define NS 100   // seq len
#define NM 50    // memory slots
#define ND 128   // dim
#define T  384   // threads: 256 compute + 128 mem
#define AS 52    // padded attn row stride (floats, 16B-aligned rows)

#define NROW (NB * NS)     // 12800 (b,s) rows
#define RPB  32            // rows per precompute block
#define KS   132           // padded key row stride

// Scratch: attention weights, qe@W1b+b1, fused matrix M = W2@[er|ad], bias
__device__ float g_attn[NB * NS * NM];
__device__ float g_q1[NB * NS * ND];
__device__ __half g_M[ND * 2 * ND];     // [k][j], j in 0..255 (e then a)
__device__ float  g_bias[2 * ND];       // b2@[er|ad] + [er_b|ad_b]

#define BAR256()         asm volatile("bar.sync 1, 256;" ::: "memory")

__device__ __forceinline__ float tanh_fast(float x) {
    float y;
    asm("tanh.approx.f32 %0, %1;" : "=f"(y) : "f"(x));
    return y;
}
__device__ __forceinline__ float sigmoid_fast(float x) {
    return fmaf(0.5f, tanh_fast(0.5f * x), 0.5f);
}

// ---------------------------------------------------------------------------
// K0: combine W2 with er/ad:  M[k][j] = sum_i W2[k][i]*E[i][j],
//     bias[j] = sum_i b2[i]*E[i][j] + eb[j].   grid=128 (k), block=256 (j).
// ---------------------------------------------------------------------------
__global__ __launch_bounds__(256, 1)
void combine_kernel(const float* __restrict__ vu_w2,
                    const float* __restrict__ vu_b2,
                    const float* __restrict__ er_w,
                    const float* __restrict__ er_b,
                    const float* __restrict__ ad_w,
                    const float* __restrict__ ad_b) {
    __shared__ float w2row[ND];
    const int k = blockIdx.x;
    const int j = threadIdx.x;
    for (int i = j; i < ND; i += 256) w2row[i] = vu_w2[k * ND + i];
    __syncthreads();
    const float* E = (j < ND) ? er_w : ad_w;
    const int jj = j & (ND - 1);
    float acc = 0.f;
#pragma unroll 8
    for (int i = 0; i < ND; i++) acc = fmaf(w2row[i], E[i * ND + jj], acc);
    g_M[k * 2 * ND + j] = __float2half_rn(acc);
    if (k == 0) {
        float bacc = (j < ND) ? er_b[jj] : ad_b[jj];
        for (int i = 0; i < ND; i++) bacc = fmaf(vu_b2[i], E[i * ND + jj], bacc);
        g_bias[j] = bacc;
    }
}

// ---------------------------------------------------------------------------
// K1: tiled batched precompute. w1b stored fp16 in smem (math fp32) so the
// block fits 75KB -> 2 blocks/SM (16 warps), halving waves + doubling issue.
// ---------------------------------------------------------------------------
#define P_KEY  0
#define P_W1BH (NM * KS)                    // 6600 (halves; 8192 float slots)
#define P_QE   (P_W1BH + ND * ND / 2)       // 14792
#define P_B1   (P_QE + RPB * ND)            // 18888
#define P_IDS  (P_B1 + ND)                  // 19016
#define P_TOTF (P_IDS + RPB)
#define PRE_SMEM_BYTES (P_TOTF * 4)

__global__ __launch_bounds__(256, 2)
void precompute_kernel(const int* __restrict__ qseq,
                       const float* __restrict__ emb,
                       const float* __restrict__ keym,
                       const float* __restrict__ vu_w1,
                       const float* __restrict__ vu_b1) {
    extern __shared__ float ps[];
    float*  sKey  = ps + P_KEY;
    __half* sW1bh = (__half*)(ps + P_W1BH);
    float*  sQe   = ps + P_QE;
    float*  sB1   = ps + P_B1;
    int*    sIds  = (int*)(ps + P_IDS);

    const int t  = threadIdx.x;
    const int r0 = blockIdx.x * RPB;

    if (t < RPB) sIds[t] = qseq[r0 + t];

    for (int i = t; i < NM * ND / 4; i += 256) {
        const int m = i / 32, c4 = i % 32;
        *(float4*)(sKey + m * KS + c4 * 4) = ((const float4*)keym)[i];
    }
    // w1b (rows 128..255 of vu_w1) -> fp16 smem
    {
        const float4* src = (const float4*)(vu_w1 + ND * ND);
        for (int i = t; i < ND * ND / 4; i += 256) {
            const float4 w = src[i];
            const __half2 h01 = __floats2half2_rn(w.x, w.y);
            const __half2 h23 = __floats2half2_rn(w.z, w.w);
            uint2 o;
            o.x = *(const unsigned*)&h01;
            o.y = *(const unsigned*)&h23;
            ((uint2*)sW1bh)[i] = o;
        }
    }
    if (t < ND) sB1[t] = vu_b1[t];
    __syncthreads();

    for (int i = t; i < RPB * 32; i += 256) {
        const int row = i >> 5, c4 = i & 31;
        const float4* src = (const float4*)(emb + (size_t)sIds[row] * ND);
        *(float4*)(sQe + row * ND + c4 * 4) = src[c4];
    }
    __syncthreads();

    // ---- logits + softmax (fp32, unchanged) ----
    {
        const int wid = t >> 5, lid = t & 31;
        const int mB = (lid < NM - 32) ? lid + 32 : lid;
        float acc0[4] = {0, 0, 0, 0}, acc1[4] = {0, 0, 0, 0};
        const float* kA = sKey + lid * KS;
        const float* kB = sKey + mB * KS;
#pragma unroll 8
        for (int k4 = 0; k4 < 32; k4++) {
            const float4 a = *(const float4*)(kA + k4 * 4);
            const float4 b = *(const float4*)(kB + k4 * 4);
#pragma unroll
            for (int r = 0; r < 4; r++) {
                const float4 q = *(const float4*)(sQe + (wid * 4 + r) * ND + k4 * 4);
                acc0[r] = fmaf(q.x, a.x, fmaf(q.y, a.y, fmaf(q.z, a.z, fmaf(q.w, a.w, acc0[r]))));
                acc1[r] = fmaf(q.x, b.x, fmaf(q.y, b.y, fmaf(q.z, b.z, fmaf(q.w, b.w, acc1[r]))));
            }
        }
        const bool hasB = (lid < NM - 32);
#pragma unroll
        for (int r = 0; r < 4; r++) {
            float v0 = acc0[r];
            float v1 = hasB ? acc1[r] : -1e30f;
            float mx = fmaxf(v0, v1);
#pragma unroll
            for (int o = 16; o; o >>= 1) mx = fmaxf(mx, __shfl_xor_sync(0xffffffffu, mx, o));
            float e0 = __expf(v0 - mx);
            float e1 = hasB ? __expf(v1 - mx) : 0.f;
            float sum = e0 + e1;
#pragma unroll
            for (int o = 16; o; o >>= 1) sum += __shfl_xor_sync(0xffffffffu, sum, o);
            const float inv = 1.f / sum;
            float* dst = g_attn + (size_t)(r0 + wid * 4 + r) * NM;
            dst[lid] = e0 * inv;
            if (hasB) dst[lid + 32] = e1 * inv;
        }
    }

    // ---- q1 = qe @ w1b + b1 : fp16 weights, fp32 math ----
    {
        const int cg = t & 31;
        const int rg = t >> 5;
        float4 acc[4] = {{0,0,0,0},{0,0,0,0},{0,0,0,0},{0,0,0,0}};
#pragma unroll 4
        for (int k4 = 0; k4 < 32; k4++) {
            const uint2 raw0 = *(const uint2*)(sW1bh + (k4 * 4 + 0) * ND + cg * 4);
            const uint2 raw1 = *(const uint2*)(sW1bh + (k4 * 4 + 1) * ND + cg * 4);
            const uint2 raw2 = *(const uint2*)(sW1bh + (k4 * 4 + 2) * ND + cg * 4);
            const uint2 raw3 = *(const uint2*)(sW1bh + (k4 * 4 + 3) * ND + cg * 4);
            const float2 w0a = __half22float2(*(const __half2*)&raw0.x);
            const float2 w0b = __half22float2(*(const __half2*)&raw0.y);
            const float2 w1a = __half22float2(*(const __half2*)&raw1.x);
            const float2 w1b_ = __half22float2(*(const __half2*)&raw1.y);
            const float2 w2a = __half22float2(*(const __half2*)&raw2.x);
            const float2 w2b = __half22float2(*(const __half2*)&raw2.y);
            const float2 w3a = __half22float2(*(const __half2*)&raw3.x);
            const float2 w3b = __half22float2(*(const __half2*)&raw3.y);
#pragma unroll
            for (int r = 0; r < 4; r++) {
                const float4 q = *(const float4*)(sQe + (rg * 4 + r) * ND + k4 * 4);
                acc[r].x = fmaf(q.x, w0a.x, fmaf(q.y, w1a.x, fmaf(q.z, w2a.x, fmaf(q.w, w3a.x, acc[r].x))));
                acc[r].y = fmaf(q.x, w0a.y, fmaf(q.y, w1a.y, fmaf(q.z, w2a.y, fmaf(q.w, w3a.y, acc[r].y))));
                acc[r].z = fmaf(q.x, w0b.x, fmaf(q.y, w1b_.x, fmaf(q.z, w2b.x, fmaf(q.w, w3b.x, acc[r].z))));
                acc[r].w = fmaf(q.x, w0b.y, fmaf(q.y, w1b_.y, fmaf(q.z, w2b.y, fmaf(q.w, w3b.y, acc[r].w))));
            }
        }
        const float4 b4 = *(const float4*)(sB1 + cg * 4);
#pragma unroll
        for (int r = 0; r < 4; r++) {
            float4 o = acc[r];
            o.x += b4.x; o.y += b4.y; o.z += b4.z; o.w += b4.w;
            *(float4*)(g_q1 + (size_t)(r0 + rg * 4 + r) * ND + cg * 4) = o;
        }
    }
}

// ---------------------------------------------------------------------------
// K2: warp-specialized recurrent kernel (unchanged from R12).
// ---------------------------------------------------------------------------
// smem layout (floats)
#define SM_W1H  0                         // 128*128 half = 8192 floats
#define SM_ATTN 8192                      // 100*52 = 5200 (padded rows)
#define SM_PA   13392                     // 1024 (A partials)
#define SM_PC   14416                     // 2 x 1024 (pre-act partials, parity)
#define SM_READ 16464                     // 128 (tail only)
#define SM_H    16592                     // 128 (tail only)
#define SM_UP   16720                     // 128 (tail only)
#define SM_BE   16848                     // 128 (bias_e)
#define SM_BA   16976                     // 128 (bias_a)
#define SM_R0   17104                     // 2 x 256 (parity x 2 halves)
#define SM_G    17616                     // 2 x 256
#define SM_C    18128                     // 2 x 2 (+4 pad)
#define SM_V    18136                     // 50*128 = 6400
#define SM_TOTF (SM_V + NM * ND)
#define SMEM_BYTES (SM_TOTF * 4)

__global__ __launch_bounds__(T, 1)
void recurrent_kernel(const int* __restrict__ qseq,
                      const float* __restrict__ emb,
                      const float* __restrict__ vu_w1,
                      const float* __restrict__ out_w1,
                      const float* __restrict__ out_b1,
                      const float* __restrict__ out_w2,
                      const float* __restrict__ out_b2,
                      float* __restrict__ out) {
    extern __shared__ float sm[];
    __half* sW1h = (__half*)(sm + SM_W1H);
    float* sAttn = sm + SM_ATTN;
    float* sPA   = sm + SM_PA;
    float* sPC   = sm + SM_PC;
    float* sRead = sm + SM_READ;
    float* sH    = sm + SM_H;
    float* sUp   = sm + SM_UP;
    float* sV    = sm + SM_V;

    const int b = blockIdx.x;
    const int t = threadIdx.x;

    // ---- shared init ----
    for (int i = t; i < ND * ND; i += T) sW1h[i] = __float2half_rn(vu_w1[i]);
    for (int i = t; i < NS * NM; i += T)
        sAttn[(i / NM) * AS + (i % NM)] = g_attn[b * NS * NM + i];
    for (int i = t; i < 2 * 1024; i += T) sPC[i] = 0.f;
    for (int i = t; i < 1032; i += T) sm[SM_R0 + i] = 0.f;   // r0/g/c region
    for (int i = t; i < NM * ND; i += T) sV[i] = 0.f;
    if (t < ND) {
        sm[SM_BE + t] = g_bias[t];
        sm[SM_BA + t] = g_bias[ND + t];
    }

    // ---- compute-role registers: fused matrix M as packed half2 ----
    const int lid = t & 31;
    const int jq = t & 63;            // output quad (256 outputs / 4)
    const int ks = (t >> 6) & 3;      // k-slice of 32
    __half2 mh01[32], mh23[32];
    if (t < 256) {
#pragma unroll
        for (int kk = 0; kk < 32; kk++) {
            const uint2 raw = *(const uint2*)(g_M + (ks * 32 + kk) * 2 * ND + jq * 4);
            mh01[kk] = *(const __half2*)&raw.x;
            mh23[kk] = *(const __half2*)&raw.y;
        }
    }
    // mem-role mapping: 2 d-columns, half m-range
    const int u2 = t - 256;           // 0..127
    const int hh = u2 >> 6;           // m-half: 0 -> m 0..23, 1 -> m 24..49
    const int c2 = (u2 & 63) * 2;     // d-column pair

    // compute stage mappings
    const int j4 = (t & 31) * 4;
    const int kg = (t >> 5) & 7;              // compute warp id
    const int kownA = kg * 16 + (lid & 15);   // A slice (16 k per warp)
    const int kownC = ks * 32 + lid;          // M slice (32 k per warp)

    __syncthreads();

    const float* q1b = g_q1 + b * NS * ND;

    for (int s = 0; s < NS; s++) {
        const int par  = s & 1;         // sPC written; r0/g/c consumed
        const int parm = (s + 1) & 1;   // sPC from prev step; r0/g/c written

        if (t < 256) {
            const float q1f = q1b[s * ND + kownC];
            const float* pc = sPC + parm * 1024;

            // ---- A prologue: reconstruct e/a at kownA, then read value ----
            float rd;
            {
                float pe = sm[SM_BE + kownA];
                float pa = sm[SM_BA + kownA];
#pragma unroll
                for (int g = 0; g < 4; g++) {
                    pe += pc[g * 256 + kownA];
                    pa += pc[g * 256 + 128 + kownA];
                }
                const float e = sigmoid_fast(pe);
                const float a = tanh_fast(pa);
                const float r0 = sm[SM_R0 + par * 256 + kownA]
                               + sm[SM_R0 + par * 256 + 128 + kownA];
                const float gg = sm[SM_G + par * 256 + kownA]
                               + sm[SM_G + par * 256 + 128 + kownA];
                const float cc = sm[SM_C + par * 2] + sm[SM_C + par * 2 + 1];
                rd = fmaf(cc, a, fmaf(-e, gg, r0));
            }
            // ---- A GEMV (fp16): x as dup'd half2 broadcast via shfl ----
            {
                const __half2 rh2 = __float2half2_rn(rd);
                const unsigned ru = *(const unsigned*)&rh2;
                __half2 acc01 = __floats2half2_rn(0.f, 0.f);
                __half2 acc23 = acc01;
                const __half* wrow = sW1h + (kg * 16) * ND + j4;
#pragma unroll
                for (int i = 0; i < 16; i++) {
                    const unsigned xs = __shfl_sync(0xffffffffu, ru, i);
                    const __half2 xh = *(const __half2*)&xs;
                    const uint2 raw = *(const uint2*)(wrow + i * ND);
                    acc01 = __hfma2(xh, *(const __half2*)&raw.x, acc01);
                    acc23 = __hfma2(xh, *(const __half2*)&raw.y, acc23);
                }
                const float2 f01 = __half22float2(acc01);
                const float2 f23 = __half22float2(acc23);
                float4 o = {f01.x, f01.y, f23.x, f23.y};
                *(float4*)(sPA + kg * ND + j4) = o;
            }
            BAR256();

            // ---- M prologue: h[kownC] = tanh(q1 + sum partials) ----
            float hv;
            {
                float v = q1f;
#pragma unroll
                for (int g = 0; g < 8; g++) v += sPA[g * ND + kownC];
                hv = tanh_fast(v);
            }
            // ---- M GEMV (fp16): 256 pre-act outputs ----
            {
                const __half2 hh2 = __float2half2_rn(hv);
                const unsigned hu = *(const unsigned*)&hh2;
                __half2 acc01 = __floats2half2_rn(0.f, 0.f);
                __half2 acc23 = acc01;
#pragma unroll
                for (int i = 0; i < 32; i++) {
                    const unsigned xs = __shfl_sync(0xffffffffu, hu, i);
                    const __half2 xh = *(const __half2*)&xs;
                    acc01 = __hfma2(xh, mh01[i], acc01);
                    acc23 = __hfma2(xh, mh23[i], acc23);
                }
                const float2 p01 = __half22float2(acc01);
                const float2 p23 = __half22float2(acc23);
                float4 o = {p01.x, p01.y, p23.x, p23.y};
                *(float4*)(sPC + par * 1024 + ks * 256 + jq * 4) = o;
            }
        } else {
            // ---- mem warps: 2 columns x half m-range ----
            const int moff = hh ? 24 : 0;
            const float* wub = sAttn + (s ? (s - 1) * AS : 0) + moff;
            const float* wsb = sAttn + s * AS + moff;
            const float* wrb = sAttn + ((s + 1 < NS) ? (s + 1) : (NS - 1)) * AS + moff;
            float2 ev, av;
            if (s == 0) {
                ev.x = ev.y = av.x = av.y = 0.f;
            } else {
                const float* pc = sPC + parm * 1024;
                float2 pe = *(const float2*)(sm + SM_BE + c2);
                float2 pa = *(const float2*)(sm + SM_BA + c2);
#pragma unroll
                for (int g = 0; g < 4; g++) {
                    const float2 q = *(const float2*)(pc + g * 256 + c2);
                    const float2 r = *(const float2*)(pc + g * 256 + 128 + c2);
                    pe.x += q.x; pe.y += q.y;
                    pa.x += r.x; pa.y += r.y;
                }
                ev.x = sigmoid_fast(pe.x); ev.y = sigmoid_fast(pe.y);
                av.x = tanh_fast(pa.x);    av.y = tanh_fast(pa.y);
            }
            const float nex = -ev.x, ney = -ev.y;
            float2 r0v = {0.f, 0.f}, gv = {0.f, 0.f};
            float cacc = 0.f;

#define MEM2(wum, wsm, wrm, m) { \
    float2 v = *(float2*)(sV + (m) * ND + c2); \
    v.x = fmaf(wum, fmaf(nex, v.x, av.x), v.x); \
    v.y = fmaf(wum, fmaf(ney, v.y, av.y), v.y); \
    *(float2*)(sV + (m) * ND + c2) = v; \
    const float px = (wrm) * v.x, py = (wrm) * v.y; \
    r0v.x += px; r0v.y += py; \
    gv.x = fmaf(wsm, px, gv.x); gv.y = fmaf(wsm, py, gv.y); \
    cacc = fmaf(wrm, wsm, cacc); }

#pragma unroll
            for (int q = 0; q < 6; q++) {
                const float4 wu4 = *(const float4*)(wub + q * 4);
                const float4 ws4 = *(const float4*)(wsb + q * 4);
                const float4 wr4 = *(const float4*)(wrb + q * 4);
                MEM2(wu4.x, ws4.x, wr4.x, moff + q * 4 + 0)
                MEM2(wu4.y, ws4.y, wr4.y, moff + q * 4 + 1)
                MEM2(wu4.z, ws4.z, wr4.z, moff + q * 4 + 2)
                MEM2(wu4.w, ws4.w, wr4.w, moff + q * 4 + 3)
            }
            if (hh) {
                const float2 wu2 = *(const float2*)(wub + 24);
                const float2 ws2 = *(const float2*)(wsb + 24);
                const float2 wr2 = *(const float2*)(wrb + 24);
                MEM2(wu2.x, ws2.x, wr2.x, 48)
                MEM2(wu2.y, ws2.y, wr2.y, 49)
            }
#undef MEM2
            *(float2*)(sm + SM_R0 + parm * 256 + hh * 128 + c2) = r0v;
            *(float2*)(sm + SM_G  + parm * 256 + hh * 128 + c2) = gv;
            if ((u2 & 63) == 0) sm[SM_C + parm * 2 + hh] = cacc;
        }
        __syncthreads();
    }

    // ---- tail: read_out = w_99 . v_100 via the same identity ----
    if (t < ND) {
        const float* pc = sPC + 1024;       // parity of s=99
        float pe = sm[SM_BE + t];
        float pa = sm[SM_BA + t];
#pragma unroll
        for (int g = 0; g < 4; g++) {
            pe += pc[g * 256 + t];
            pa += pc[g * 256 + 128 + t];
        }
        const float e = sigmoid_fast(pe);
        const float a = tanh_fast(pa);
        const float r0 = sm[SM_R0 + t] + sm[SM_R0 + 128 + t];   // parity 0
        const float gg = sm[SM_G + t] + sm[SM_G + 128 + t];
        const float cc = sm[SM_C] + sm[SM_C + 1];
        sRead[t] = fmaf(cc, a, fmaf(-e, gg, r0));
        const int qi = qseq[b * NS + (NS - 1)];
        sUp[t] = emb[qi * ND + t];   // qe_last
    }
    __syncthreads();

    // ---- output head (fp32 weights from global; one-shot) ----
    if (t < 256) {
        const float* pin = (kg < 4) ? sRead : (sUp - ND);
        float4 acc = {0.f, 0.f, 0.f, 0.f};
#pragma unroll
        for (int i = 0; i < 32; i++) {
            const int k = kg * 32 + i;
            const float x = pin[k];
            const float4 w = *(const float4*)(out_w1 + k * ND + j4);
            acc.x = fmaf(x, w.x, acc.x);
            acc.y = fmaf(x, w.y, acc.y);
            acc.z = fmaf(x, w.z, acc.z);
            acc.w = fmaf(x, w.w, acc.w);
        }
        *(float4*)(sPA + kg * ND + j4) = acc;
    }
    __syncthreads();
    if (t < ND) {
        float v = out_b1[t];
#pragma unroll
        for (int g = 0; g < 8; g++) v += sPA[g * ND + t];
        sH[t] = fmaxf(v, 0.f) * out_w2[t];
    }
    __syncthreads();
    if (t < 32) {
        float v = sH[t] + sH[t + 32] + sH[t + 64] + sH[t + 96];
#pragma unroll
        for (int o = 16; o; o >>= 1) v += __shfl_xor_sync(0xffffffffu, v, o);
        if (t == 0) out[b] = 1.f / (1.f + __expf(-(v + out_b2[0])));
    }
}

// ---------------------------------------------------------------------------
extern "C" void kernel_launch(void* const* d_in, const int* in_sizes, int n_in,
                              void* d_out, int out_size) {
    const int*   qseq   = (const int*)  d_in[0];
    // d_in[1] = answer_seq (unused by reference)
    const float* emb    = (const float*)d_in[2];
    const float* keym   = (const float*)d_in[3];
    const float* vu_w1  = (const float*)d_in[4];
    const float* vu_b1  = (const float*)d_in[5];
    const float* vu_w2  = (const float*)d_in[6];
    const float* vu_b2  = (const float*)d_in[7];
    const float* er_w   = (const float*)d_in[8];
    const float* er_b   = (const float*)d_in[9];
    const float* ad_w   = (const float*)d_in[10];
    const float* ad_b   = (const float*)d_in[11];
    const float* out_w1 = (const float*)d_in[12];
    const float* out_b1 = (const float*)d_in[13];
    const float* out_w2 = (const float*)d_in[14];
    const float* out_b2 = (const float*)d_in[15];
    float* out = (float*)d_out;

    cudaFuncSetAttribute(precompute_kernel,
                         cudaFuncAttributeMaxDynamicSharedMemorySize, PRE_SMEM_BYTES);
    cudaFuncSetAttribute(recurrent_kernel,
                         cudaFuncAttributeMaxDynamicSharedMemorySize, SMEM_BYTES);

    precompute_kernel<<<NROW / RPB, 256, PRE_SMEM_BYTES>>>(qseq, emb, keym, vu_w1, vu_b1);
    combine_kernel<<<ND, 256>>>(vu_w2, vu_b2, er_w, er_b, ad_w, ad_b);
    recurrent_kernel<<<NB, T, SMEM_BYTES>>>(qseq, emb, vu_w1,
                                            out_w1, out_b1, out_w2, out_b2, out);
}